// round 14
// baseline (speedup 1.0000x reference)
#include <cuda_runtime.h>
#include <cuda_bf16.h>
#include <cuda_fp16.h>
#include <math.h>
#include <stdint.h>

#define B_   2
#define T_   2048
#define DIM_ 1024
#define NH_  16
#define HD_  64

// fp32 scratch
__device__ float g_qkv[(size_t)B_ * T_ * 3 * DIM_];

// packed fp16-pair scratch
__device__ uint32_t g_ahi[(size_t)4096 * 512];                 // A hi pairs
__device__ uint32_t g_alo[(size_t)4096 * 512];                 // A lo pairs
__device__ uint32_t g_wt [(size_t)3072 * 512];                 // W transposed, single fp16
__device__ uint32_t g_qhi[(size_t)B_ * NH_ * T_ * 32];         // q hi pairs (scaled)
__device__ uint32_t g_qlo[(size_t)B_ * NH_ * T_ * 32];         // q lo pairs
__device__ uint32_t g_kh [(size_t)B_ * NH_ * T_ * 32];         // k single
__device__ uint32_t g_vt [(size_t)B_ * NH_ * HD_ * (T_ / 2)];  // v transposed single

__device__ __forceinline__ void mma_fp16(float c[4], const uint32_t a[4],
                                         const uint32_t b[2]) {
    asm volatile(
        "mma.sync.aligned.m16n8k16.row.col.f32.f16.f16.f32 "
        "{%0,%1,%2,%3}, {%4,%5,%6,%7}, {%8,%9}, {%0,%1,%2,%3};\n"
        : "+f"(c[0]), "+f"(c[1]), "+f"(c[2]), "+f"(c[3])
        : "r"(a[0]), "r"(a[1]), "r"(a[2]), "r"(a[3]), "r"(b[0]), "r"(b[1]));
}

__device__ __forceinline__ void ldm_x4(uint32_t r[4], uint32_t addr) {
    asm volatile("ldmatrix.sync.aligned.m8n8.x4.shared.b16 {%0,%1,%2,%3}, [%4];\n"
                 : "=r"(r[0]), "=r"(r[1]), "=r"(r[2]), "=r"(r[3])
                 : "r"(addr));
}

__device__ __forceinline__ uint32_t pack_h2f(float x, float y) {
    __half2 p = __floats2half2_rn(x, y);
    return *reinterpret_cast<uint32_t*>(&p);
}
__device__ __forceinline__ uint32_t pack_l2f(float x, float y) {
    float xh = __half2float(__float2half_rn(x));
    float yh = __half2float(__float2half_rn(y));
    __half2 p = __floats2half2_rn(x - xh, y - yh);
    return *reinterpret_cast<uint32_t*>(&p);
}

__device__ __forceinline__ void cp16(uint32_t dst_smem, const void* src) {
    asm volatile("cp.async.cg.shared.global [%0], [%1], 16;\n"
                 :: "r"(dst_smem), "l"(src));
}
#define CP_COMMIT() asm volatile("cp.async.commit_group;\n" ::: "memory")
#define CP_WAIT_1() asm volatile("cp.async.wait_group 1;\n" ::: "memory")
#define CP_WAIT_0() asm volatile("cp.async.wait_group 0;\n" ::: "memory")

// ===========================================================================
// conv_rows: fp32 [M][K] -> hi/lo fp16-pair [M][K/2]
// ===========================================================================
__global__ __launch_bounds__(256) void conv_rows(const float* __restrict__ src,
                                                 uint32_t* __restrict__ hi,
                                                 uint32_t* __restrict__ lo,
                                                 int npairs) {
    const int i = blockIdx.x * blockDim.x + threadIdx.x;
    if (i >= npairs) return;
    float2 f = *reinterpret_cast<const float2*>(src + (size_t)i * 2);
    hi[i] = pack_h2f(f.x, f.y);
    lo[i] = pack_l2f(f.x, f.y);
}

// ===========================================================================
// conv_tr: fp32 W[K][N] -> transposed single-fp16 pairs [N][K/2]
// ===========================================================================
__global__ __launch_bounds__(256) void conv_tr(const float* __restrict__ src,
                                               uint32_t* __restrict__ dst,
                                               int K, int N) {
    __shared__ float vs[32][33];
    const int tid = threadIdx.x;
    const int n0 = blockIdx.x * 32;
    const int k0 = blockIdx.y * 32;
    const int Kp = K >> 1;
#pragma unroll
    for (int e = 0; e < 4; e++) {
        const int idx = tid + 256 * e;
        const int kl = idx >> 5, nl = idx & 31;
        vs[kl][nl] = src[(size_t)(k0 + kl) * N + n0 + nl];
    }
    __syncthreads();
#pragma unroll
    for (int e = 0; e < 2; e++) {
        const int idx = tid + 256 * e;
        const int nl = idx >> 4, p = idx & 15;
        float f0 = vs[2 * p][nl], f1 = vs[2 * p + 1][nl];
        const size_t o = (size_t)(n0 + nl) * Kp + (k0 >> 1) + p;
        dst[o] = pack_h2f(f0, f1);
    }
}

// ===========================================================================
// gemm_pre: C = A @ B fp16 (A hi/lo split, B single). BM=128 BN=64,
// 2-stage cp.async, ldmatrix.
// Stage layout (uint32): Ahi[0..2560) Alo[2560..5120) B[5120..6400)
// ===========================================================================
#define BM 128
#define BN 64
#define SA_STRIDE 20
#define SB_STRIDE 20
#define G_STAGE 6400
#define GEMM_SMEM_BYTES (2 * G_STAGE * 4)   // 51,200

__global__ __launch_bounds__(256) void gemm_pre(const uint32_t* __restrict__ Ahi,
                                                const uint32_t* __restrict__ Alo,
                                                const uint32_t* __restrict__ Bt,
                                                float* __restrict__ C,
                                                int M, int N, int Kp) {
    extern __shared__ uint32_t sm[];
    const uint32_t sm_u32 = (uint32_t)__cvta_generic_to_shared(sm);

    const int tid  = threadIdx.x;
    const int lane = tid & 31;
    const int wid  = tid >> 5;
    const int wm   = wid & 3;
    const int wn   = wid >> 2;
    const int lr   = lane >> 2;
    const int lc   = lane & 3;
    const int lt   = lane >> 3;
    const int lrw  = lane & 7;

    const int m0 = blockIdx.y * BM;
    const int n0 = blockIdx.x * BN;

    float acc[2][4][4];
#pragma unroll
    for (int mt = 0; mt < 2; mt++)
#pragma unroll
        for (int nt = 0; nt < 4; nt++)
#pragma unroll
            for (int j = 0; j < 4; j++) acc[mt][nt][j] = 0.f;

    const int Kt = Kp / 16;

    auto prefetch = [&](int kt, int s) {
        const int k0p = kt * 16;
        const uint32_t base = sm_u32 + s * G_STAGE * 4;
#pragma unroll
        for (int j = 0; j < 2; j++) {
            const int idx = tid + 256 * j;
            const int row = idx >> 2, ch = idx & 3;
            cp16(base + (row * SA_STRIDE + ch * 4) * 4,
                 &Ahi[(size_t)(m0 + row) * Kp + k0p + ch * 4]);
            cp16(base + (2560 + row * SA_STRIDE + ch * 4) * 4,
                 &Alo[(size_t)(m0 + row) * Kp + k0p + ch * 4]);
        }
        {
            const int row = tid >> 2, ch = tid & 3;
            cp16(base + (5120 + row * SB_STRIDE + ch * 4) * 4,
                 &Bt[(size_t)(n0 + row) * Kp + k0p + ch * 4]);
        }
    };

    prefetch(0, 0);
    CP_COMMIT();

    for (int kt = 0; kt < Kt; kt++) {
        if (kt + 1 < Kt) {
            prefetch(kt + 1, (kt + 1) & 1);
            CP_COMMIT();
            CP_WAIT_1();
        } else {
            CP_WAIT_0();
        }
        __syncthreads();

        const uint32_t sbase = sm_u32 + (kt & 1) * G_STAGE * 4;

#pragma unroll
        for (int ks = 0; ks < 2; ks++) {
            uint32_t ahi[2][4], alo[2][4];
#pragma unroll
            for (int mt = 0; mt < 2; mt++) {
                const int m = wm * 32 + mt * 16 + (lt & 1) * 8 + lrw;
                const uint32_t off = (uint32_t)(m * SA_STRIDE + ks * 8 + (lt >> 1) * 4) * 4;
                ldm_x4(ahi[mt], sbase + off);
                ldm_x4(alo[mt], sbase + 2560 * 4 + off);
            }
#pragma unroll
            for (int ntp = 0; ntp < 2; ntp++) {
                const int n = wn * 32 + ntp * 16 + (lt >> 1) * 8 + lrw;
                const uint32_t off = (uint32_t)(n * SB_STRIDE + ks * 8 + (lt & 1) * 4) * 4;
                uint32_t th[4];
                ldm_x4(th, sbase + 5120 * 4 + off);
                uint32_t bh0[2] = {th[0], th[1]}, bh1[2] = {th[2], th[3]};
#pragma unroll
                for (int mt = 0; mt < 2; mt++) {
                    mma_fp16(acc[mt][2 * ntp],     ahi[mt], bh0);
                    mma_fp16(acc[mt][2 * ntp],     alo[mt], bh0);
                    mma_fp16(acc[mt][2 * ntp + 1], ahi[mt], bh1);
                    mma_fp16(acc[mt][2 * ntp + 1], alo[mt], bh1);
                }
            }
        }
        __syncthreads();
    }

#pragma unroll
    for (int mt = 0; mt < 2; mt++) {
#pragma unroll
        for (int nt = 0; nt < 4; nt++) {
            const int row0 = m0 + wm * 32 + mt * 16 + lr;
            const int col  = n0 + wn * 32 + nt * 8 + lc * 2;
            float2 v0 = make_float2(acc[mt][nt][0], acc[mt][nt][1]);
            float2 v1 = make_float2(acc[mt][nt][2], acc[mt][nt][3]);
            *reinterpret_cast<float2*>(&C[(size_t)row0 * N + col]) = v0;
            *reinterpret_cast<float2*>(&C[(size_t)(row0 + 8) * N + col]) = v1;
        }
    }
}

// ===========================================================================
// rope_conv: RoPE q,k; q scaled 0.125 -> fp16 hi/lo; k -> fp16 single
// ===========================================================================
__global__ __launch_bounds__(256) void rope_conv(const float* __restrict__ sin_t,
                                                 const float* __restrict__ cos_t) {
    const int idx = blockIdx.x * blockDim.x + threadIdx.x;
    const int total = B_ * T_ * NH_ * (HD_ / 2);
    if (idx >= total) return;
    const int i = idx & 31;
    const int h = (idx >> 5) & (NH_ - 1);
    const int bt = idx >> 9;
    const int t = bt & (T_ - 1);
    const int b = bt >> 11;

    const float s = sin_t[t * HD_ + 2 * i];
    const float c = cos_t[t * HD_ + 2 * i];

    const float* row = g_qkv + (size_t)bt * (3 * DIM_);
    const size_t o = ((size_t)(b * NH_ + h) * T_ + t) * 32 + i;

    float2 q = *reinterpret_cast<const float2*>(row + h * HD_ + 2 * i);
    float q0 = (q.x * c - q.y * s) * 0.125f;
    float q1 = (q.y * c + q.x * s) * 0.125f;
    g_qhi[o] = pack_h2f(q0, q1);
    g_qlo[o] = pack_l2f(q0, q1);

    float2 k = *reinterpret_cast<const float2*>(row + DIM_ + h * HD_ + 2 * i);
    float k0 = k.x * c - k.y * s;
    float k1 = k.y * c + k.x * s;
    g_kh[o] = pack_h2f(k0, k1);
}

// ===========================================================================
// vtrans_conv: V fp32 -> transposed fp16x2 [b,h,d,t]
// ===========================================================================
__global__ __launch_bounds__(256) void vtrans_conv() {
    __shared__ float vs[64][65];
    const int tid = threadIdx.x;
    const int t0 = blockIdx.x * 64;
    const int h  = blockIdx.y;
    const int b  = blockIdx.z;

    const int r = tid >> 2;
    const int q = (tid & 3) * 16;
    const float* src = g_qkv + (size_t)(b * T_ + t0 + r) * (3 * DIM_) + 2 * DIM_ + h * HD_;
#pragma unroll
    for (int v = 0; v < 4; v++) {
        float4 f4 = *reinterpret_cast<const float4*>(src + q + v * 4);
        vs[r][q + v * 4 + 0] = f4.x;
        vs[r][q + v * 4 + 1] = f4.y;
        vs[r][q + v * 4 + 2] = f4.z;
        vs[r][q + v * 4 + 3] = f4.w;
    }
    __syncthreads();

    const int Tp = T_ / 2;
#pragma unroll
    for (int j = 0; j < 8; j++) {
        const int c = tid + 256 * j;
        const int d = c >> 5, p = c & 31;
        float f0 = vs[2 * p][d], f1 = vs[2 * p + 1][d];
        const size_t o = ((size_t)(b * NH_ + h) * HD_ + d) * Tp + (t0 >> 1) + p;
        g_vt[o] = pack_h2f(f0, f1);
    }
}

// ===========================================================================
// Flash attention (R13): BQ=128, all-fp16 MMAs.
// Output written as fp16 hi/lo pairs into g_ahi/g_alo.
// ===========================================================================
#define FS 36
#define F_STAGE 4608
#define FA_SMEM_BYTES ((9216 + 2 * F_STAGE) * 4)   // 73,728

__global__ __launch_bounds__(256, 2) void flash_mma(uint32_t* __restrict__ yhi,
                                                    uint32_t* __restrict__ ylo) {
    extern __shared__ uint32_t sm[];
    const uint32_t sm_u32 = (uint32_t)__cvta_generic_to_shared(sm);
    uint32_t* Qhi = sm;
    uint32_t* Qlo = Qhi + 128 * FS;

    const int tid  = threadIdx.x;
    const int lane = tid & 31;
    const int wid  = tid >> 5;
    const int lr   = lane >> 2;
    const int lc   = lane & 3;
    const int lt   = lane >> 3;
    const int lrw  = lane & 7;

    const int qt = (T_ / 128 - 1) - blockIdx.x;
    const int h  = blockIdx.y;
    const int b  = blockIdx.z;
    const int q0 = qt * 128;
    const size_t hb = (size_t)(b * NH_ + h);
    const int Tp = T_ / 2;

#pragma unroll
    for (int j = 0; j < 8; j++) {
        const int c = tid + 256 * j;
        const int row = c >> 4, cc = c & 15;
        uint2 vh = *reinterpret_cast<const uint2*>(
            &g_qhi[(hb * T_ + q0 + row) * 32 + cc * 2]);
        uint2 vl = *reinterpret_cast<const uint2*>(
            &g_qlo[(hb * T_ + q0 + row) * 32 + cc * 2]);
        *reinterpret_cast<uint2*>(&Qhi[row * FS + cc * 2]) = vh;
        *reinterpret_cast<uint2*>(&Qlo[row * FS + cc * 2]) = vl;
    }

    auto prefetch_kv = [&](int kt, int s) {
        const uint32_t base = sm_u32 + (9216 + s * F_STAGE) * 4;
#pragma unroll
        for (int j = 0; j < 2; j++) {
            const int idx = tid + 256 * j;
            const int row = idx >> 3, ch = idx & 7;
            const uint32_t soff = (row * FS + ch * 4) * 4;
            cp16(base + soff,
                 &g_kh[(hb * T_ + kt * 64 + row) * 32 + ch * 4]);
            cp16(base + 2304 * 4 + soff,
                 &g_vt[(hb * HD_ + row) * Tp + kt * 32 + ch * 4]);
        }
    };

    float O[8][4];
#pragma unroll
    for (int nt = 0; nt < 8; nt++)
#pragma unroll
        for (int j = 0; j < 4; j++) O[nt][j] = 0.f;
    float m0 = -INFINITY, m1 = -INFINITY, l0 = 0.f, l1 = 0.f;

    const int kt_max = 2 * qt + 1;

    prefetch_kv(0, 0);
    CP_COMMIT();

    const int qm = wid * 16 + (lt & 1) * 8 + lrw;
    const int nrow_base = (lt >> 1) * 8 + lrw;

    for (int kt = 0; kt <= kt_max; kt++) {
        if (kt < kt_max) {
            prefetch_kv(kt + 1, (kt + 1) & 1);
            CP_COMMIT();
            CP_WAIT_1();
        } else {
            CP_WAIT_0();
        }
        __syncthreads();

        const uint32_t kbase = sm_u32 + (9216 + (kt & 1) * F_STAGE) * 4;

        const int rel = kt * 64 - q0;
        if (rel <= wid * 16 + 15) {
            float sf[8][4];
#pragma unroll
            for (int nt = 0; nt < 8; nt++)
#pragma unroll
                for (int j = 0; j < 4; j++) sf[nt][j] = 0.f;

#pragma unroll
            for (int ks = 0; ks < 4; ks++) {
                const uint32_t qoff = (uint32_t)(qm * FS + ks * 8 + (lt >> 1) * 4) * 4;
                uint32_t ahi[4], alo[4];
                ldm_x4(ahi, sm_u32 + qoff);
                ldm_x4(alo, sm_u32 + 4608 * 4 + qoff);
#pragma unroll
                for (int ntp = 0; ntp < 4; ntp++) {
                    const int n = ntp * 16 + nrow_base;
                    const uint32_t koff = (uint32_t)(n * FS + ks * 8 + (lt & 1) * 4) * 4;
                    uint32_t th[4];
                    ldm_x4(th, kbase + koff);
                    uint32_t bh0[2] = {th[0], th[1]}, bh1[2] = {th[2], th[3]};
                    mma_fp16(sf[2 * ntp],     ahi, bh0);
                    mma_fp16(sf[2 * ntp],     alo, bh0);
                    mma_fp16(sf[2 * ntp + 1], ahi, bh1);
                    mma_fp16(sf[2 * ntp + 1], alo, bh1);
                }
            }

            if (rel + 63 > wid * 16) {
                const int r0 = wid * 16 + lr;
#pragma unroll
                for (int nt = 0; nt < 8; nt++) {
                    const int c0 = rel + nt * 8 + 2 * lc;
                    if (c0 > r0)         sf[nt][0] = -INFINITY;
                    if (c0 + 1 > r0)     sf[nt][1] = -INFINITY;
                    if (c0 > r0 + 8)     sf[nt][2] = -INFINITY;
                    if (c0 + 1 > r0 + 8) sf[nt][3] = -INFINITY;
                }
            }

            float ml0 = -INFINITY, ml1 = -INFINITY;
#pragma unroll
            for (int nt = 0; nt < 8; nt++) {
                ml0 = fmaxf(ml0, fmaxf(sf[nt][0], sf[nt][1]));
                ml1 = fmaxf(ml1, fmaxf(sf[nt][2], sf[nt][3]));
            }
            ml0 = fmaxf(ml0, __shfl_xor_sync(0xffffffffu, ml0, 1));
            ml0 = fmaxf(ml0, __shfl_xor_sync(0xffffffffu, ml0, 2));
            ml1 = fmaxf(ml1, __shfl_xor_sync(0xffffffffu, ml1, 1));
            ml1 = fmaxf(ml1, __shfl_xor_sync(0xffffffffu, ml1, 2));

            const float mn0 = fmaxf(m0, ml0);
            const float mn1 = fmaxf(m1, ml1);
            const float al0 = __expf(m0 - mn0);
            const float al1 = __expf(m1 - mn1);

            float rs0 = 0.f, rs1 = 0.f;
#pragma unroll
            for (int nt = 0; nt < 8; nt++) {
                sf[nt][0] = __expf(sf[nt][0] - mn0);
                sf[nt][1] = __expf(sf[nt][1] - mn0);
                sf[nt][2] = __expf(sf[nt][2] - mn1);
                sf[nt][3] = __expf(sf[nt][3] - mn1);
                rs0 += sf[nt][0] + sf[nt][1];
                rs1 += sf[nt][2] + sf[nt][3];
            }
            rs0 += __shfl_xor_sync(0xffffffffu, rs0, 1);
            rs0 += __shfl_xor_sync(0xffffffffu, rs0, 2);
            rs1 += __shfl_xor_sync(0xffffffffu, rs1, 1);
            rs1 += __shfl_xor_sync(0xffffffffu, rs1, 2);

            l0 = l0 * al0 + rs0;
            l1 = l1 * al1 + rs1;
            m0 = mn0; m1 = mn1;
#pragma unroll
            for (int nt = 0; nt < 8; nt++) {
                O[nt][0] *= al0; O[nt][1] *= al0;
                O[nt][2] *= al1; O[nt][3] *= al1;
            }

#pragma unroll
            for (int ks = 0; ks < 4; ks++) {
                uint32_t ph[4], pl[4];
                ph[0] = pack_h2f(sf[2 * ks][0],     sf[2 * ks][1]);
                ph[1] = pack_h2f(sf[2 * ks][2],     sf[2 * ks][3]);
                ph[2] = pack_h2f(sf[2 * ks + 1][0], sf[2 * ks + 1][1]);
                ph[3] = pack_h2f(sf[2 * ks + 1][2], sf[2 * ks + 1][3]);
                pl[0] = pack_l2f(sf[2 * ks][0],     sf[2 * ks][1]);
                pl[1] = pack_l2f(sf[2 * ks][2],     sf[2 * ks][3]);
                pl[2] = pack_l2f(sf[2 * ks + 1][0], sf[2 * ks + 1][1]);
                pl[3] = pack_l2f(sf[2 * ks + 1][2], sf[2 * ks + 1][3]);
#pragma unroll
                for (int ntp = 0; ntp < 4; ntp++) {
                    const int n = ntp * 16 + nrow_base;
                    const uint32_t voff = (uint32_t)(n * FS + ks * 8 + (lt & 1) * 4) * 4;
                    uint32_t tv[4];
                    ldm_x4(tv, kbase + 2304 * 4 + voff);
                    uint32_t v0[2] = {tv[0], tv[1]}, v1[2] = {tv[2], tv[3]};
                    mma_fp16(O[2 * ntp],     ph, v0);
                    mma_fp16(O[2 * ntp],     pl, v0);
                    mma_fp16(O[2 * ntp + 1], ph, v1);
                    mma_fp16(O[2 * ntp + 1], pl, v1);
                }
            }
        }
        __syncthreads();
    }

    const float inv0 = 1.0f / l0;
    const float inv1 = 1.0f / l1;
    const int r0 = q0 + wid * 16 + lr;
#pragma unroll
    for (int nt = 0; nt < 8; nt++) {
        const int pcol = h * 32 + nt * 4 + lc;
        float a = O[nt][0] * inv0, bb = O[nt][1] * inv0;
        float ccv = O[nt][2] * inv1, d = O[nt][3] * inv1;
        yhi[(size_t)(b * T_ + r0) * 512 + pcol]     = pack_h2f(a, bb);
        ylo[(size_t)(b * T_ + r0) * 512 + pcol]     = pack_l2f(a, bb);
        yhi[(size_t)(b * T_ + r0 + 8) * 512 + pcol] = pack_h2f(ccv, d);
        ylo[(size_t)(b * T_ + r0 + 8) * 512 + pcol] = pack_l2f(ccv, d);
    }
}

// ---------------------------------------------------------------------------
// Launch
// ---------------------------------------------------------------------------
extern "C" void kernel_launch(void* const* d_in, const int* in_sizes, int n_in,
                              void* d_out, int out_size) {
    const float* x      = (const float*)d_in[0];
    const float* sin_t  = (const float*)d_in[1];
    const float* cos_t  = (const float*)d_in[2];
    const float* W_qkv  = (const float*)d_in[3];
    const float* W_proj = (const float*)d_in[4];
    float* out = (float*)d_out;

    float* qkv_ptr = nullptr;
    uint32_t *ahi, *alo, *wt;
    cudaGetSymbolAddress((void**)&qkv_ptr, g_qkv);
    cudaGetSymbolAddress((void**)&ahi, g_ahi);
    cudaGetSymbolAddress((void**)&alo, g_alo);
    cudaGetSymbolAddress((void**)&wt, g_wt);

    const int M = B_ * T_;
    const int Kp = DIM_ / 2;

    cudaFuncSetAttribute(gemm_pre, cudaFuncAttributeMaxDynamicSharedMemorySize,
                         GEMM_SMEM_BYTES);
    cudaFuncSetAttribute(flash_mma, cudaFuncAttributeMaxDynamicSharedMemorySize,
                         FA_SMEM_BYTES);

    // 1) split x; transpose W_qkv; QKV GEMM
    conv_rows<<<(M * Kp) / 256, 256>>>(x, ahi, alo, M * Kp);
    {
        dim3 g(3 * DIM_ / 32, DIM_ / 32);
        conv_tr<<<g, 256>>>(W_qkv, wt, DIM_, 3 * DIM_);
    }
    {
        dim3 g((3 * DIM_) / BN, M / BM);
        gemm_pre<<<g, 256, GEMM_SMEM_BYTES>>>(ahi, alo, wt, qkv_ptr,
                                              M, 3 * DIM_, Kp);
    }

    // 2) RoPE + fp16 q/k; transpose + fp16 v
    {
        int total = B_ * T_ * NH_ * (HD_ / 2);
        rope_conv<<<(total + 255) / 256, 256>>>(sin_t, cos_t);
    }
    {
        dim3 g(T_ / 64, NH_, B_);
        vtrans_conv<<<g, 256>>>();
    }

    // 3) Flash attention (writes fp16 split output into g_ahi/g_alo)
    {
        dim3 g(T_ / 128, NH_, B_);
        flash_mma<<<g, 256, FA_SMEM_BYTES>>>(ahi, alo);
    }

    // 4) transpose W_proj; output projection
    {
        dim3 g(DIM_ / 32, DIM_ / 32);
        conv_tr<<<g, 256>>>(W_proj, wt, DIM_, DIM_);
    }
    {
        dim3 g(DIM_ / BN, M / BM);
        gemm_pre<<<g, 256, GEMM_SMEM_BYTES>>>(ahi, alo, wt, out,
                                              M, DIM_, Kp);
    }
}

// round 15
// speedup vs baseline: 1.2624x; 1.2624x over previous
#include <cuda_runtime.h>
#include <cuda_bf16.h>
#include <cuda_fp16.h>
#include <math.h>
#include <stdint.h>

#define B_   2
#define T_   2048
#define DIM_ 1024
#define NH_  16
#define HD_  64

// fp32 scratch
__device__ float g_qkv[(size_t)B_ * T_ * 3 * DIM_];

// packed scratch
__device__ uint32_t g_ahi[(size_t)4096 * 512];                 // bf16 hi pairs
__device__ uint32_t g_alo[(size_t)4096 * 512];                 // bf16 lo pairs
__device__ uint32_t g_wthi[(size_t)3072 * 512];
__device__ uint32_t g_wtlo[(size_t)3072 * 512];
__device__ uint32_t g_qhi[(size_t)B_ * NH_ * T_ * 32];         // fp16 hi pairs (scaled q)
__device__ uint32_t g_qlo[(size_t)B_ * NH_ * T_ * 32];         // fp16 lo pairs
__device__ uint32_t g_kh [(size_t)B_ * NH_ * T_ * 32];         // fp16 single (k)
__device__ uint32_t g_vt [(size_t)B_ * NH_ * HD_ * (T_ / 2)];  // fp16x2 transposed v

__device__ __forceinline__ void mma_bf16(float c[4], const uint32_t a[4],
                                         const uint32_t b[2]) {
    asm volatile(
        "mma.sync.aligned.m16n8k16.row.col.f32.bf16.bf16.f32 "
        "{%0,%1,%2,%3}, {%4,%5,%6,%7}, {%8,%9}, {%0,%1,%2,%3};\n"
        : "+f"(c[0]), "+f"(c[1]), "+f"(c[2]), "+f"(c[3])
        : "r"(a[0]), "r"(a[1]), "r"(a[2]), "r"(a[3]), "r"(b[0]), "r"(b[1]));
}

__device__ __forceinline__ void mma_fp16(float c[4], const uint32_t a[4],
                                         const uint32_t b[2]) {
    asm volatile(
        "mma.sync.aligned.m16n8k16.row.col.f32.f16.f16.f32 "
        "{%0,%1,%2,%3}, {%4,%5,%6,%7}, {%8,%9}, {%0,%1,%2,%3};\n"
        : "+f"(c[0]), "+f"(c[1]), "+f"(c[2]), "+f"(c[3])
        : "r"(a[0]), "r"(a[1]), "r"(a[2]), "r"(a[3]), "r"(b[0]), "r"(b[1]));
}

__device__ __forceinline__ void ldm_x4(uint32_t r[4], uint32_t addr) {
    asm volatile("ldmatrix.sync.aligned.m8n8.x4.shared.b16 {%0,%1,%2,%3}, [%4];\n"
                 : "=r"(r[0]), "=r"(r[1]), "=r"(r[2]), "=r"(r[3])
                 : "r"(addr));
}

__device__ __forceinline__ uint32_t pack_hi2(float x, float y) {
    __nv_bfloat162 p = {__float2bfloat16_rn(x), __float2bfloat16_rn(y)};
    return *reinterpret_cast<uint32_t*>(&p);
}
__device__ __forceinline__ uint32_t pack_lo2(float x, float y) {
    float xh = __bfloat162float(__float2bfloat16_rn(x));
    float yh = __bfloat162float(__float2bfloat16_rn(y));
    __nv_bfloat162 p = {__float2bfloat16_rn(x - xh), __float2bfloat16_rn(y - yh)};
    return *reinterpret_cast<uint32_t*>(&p);
}
__device__ __forceinline__ uint32_t pack_h2f(float x, float y) {
    __half2 p = __floats2half2_rn(x, y);
    return *reinterpret_cast<uint32_t*>(&p);
}
__device__ __forceinline__ uint32_t pack_l2f(float x, float y) {
    float xh = __half2float(__float2half_rn(x));
    float yh = __half2float(__float2half_rn(y));
    __half2 p = __floats2half2_rn(x - xh, y - yh);
    return *reinterpret_cast<uint32_t*>(&p);
}

__device__ __forceinline__ void cp16(uint32_t dst_smem, const void* src) {
    asm volatile("cp.async.cg.shared.global [%0], [%1], 16;\n"
                 :: "r"(dst_smem), "l"(src));
}
#define CP_COMMIT() asm volatile("cp.async.commit_group;\n" ::: "memory")
#define CP_WAIT_1() asm volatile("cp.async.wait_group 1;\n" ::: "memory")
#define CP_WAIT_0() asm volatile("cp.async.wait_group 0;\n" ::: "memory")

// ===========================================================================
// conv_rows: fp32 [M][K] -> hi/lo bf16-pair [M][K/2]
// ===========================================================================
__global__ __launch_bounds__(256) void conv_rows(const float* __restrict__ src,
                                                 uint32_t* __restrict__ hi,
                                                 uint32_t* __restrict__ lo,
                                                 int npairs) {
    const int i = blockIdx.x * blockDim.x + threadIdx.x;
    if (i >= npairs) return;
    float2 f = *reinterpret_cast<const float2*>(src + (size_t)i * 2);
    hi[i] = pack_hi2(f.x, f.y);
    lo[i] = pack_lo2(f.x, f.y);
}

// ===========================================================================
// conv_tr: fp32 W[K][N] -> transposed hi/lo bf16 pairs [N][K/2]
// ===========================================================================
__global__ __launch_bounds__(256) void conv_tr(const float* __restrict__ src,
                                               uint32_t* __restrict__ hi,
                                               uint32_t* __restrict__ lo,
                                               int K, int N) {
    __shared__ float vs[32][33];
    const int tid = threadIdx.x;
    const int n0 = blockIdx.x * 32;
    const int k0 = blockIdx.y * 32;
    const int Kp = K >> 1;
#pragma unroll
    for (int e = 0; e < 4; e++) {
        const int idx = tid + 256 * e;
        const int kl = idx >> 5, nl = idx & 31;
        vs[kl][nl] = src[(size_t)(k0 + kl) * N + n0 + nl];
    }
    __syncthreads();
#pragma unroll
    for (int e = 0; e < 2; e++) {
        const int idx = tid + 256 * e;
        const int nl = idx >> 4, p = idx & 15;
        float f0 = vs[2 * p][nl], f1 = vs[2 * p + 1][nl];
        const size_t o = (size_t)(n0 + nl) * Kp + (k0 >> 1) + p;
        hi[o] = pack_hi2(f0, f1);
        lo[o] = pack_lo2(f0, f1);
    }
}

// ===========================================================================
// gemm_pre (R9/R13 config): BM=128 BN=64, 2-stage cp.async, ldmatrix, bf16x3.
// ===========================================================================
#define BM 128
#define BN 64
#define SA_STRIDE 20
#define SB_STRIDE 20
#define G_STAGE 7680
#define GEMM_SMEM_BYTES (2 * G_STAGE * 4)

__global__ __launch_bounds__(256) void gemm_pre(const uint32_t* __restrict__ Ahi,
                                                const uint32_t* __restrict__ Alo,
                                                const uint32_t* __restrict__ Bthi,
                                                const uint32_t* __restrict__ Btlo,
                                                float* __restrict__ C,
                                                int M, int N, int Kp) {
    extern __shared__ uint32_t sm[];
    const uint32_t sm_u32 = (uint32_t)__cvta_generic_to_shared(sm);

    const int tid  = threadIdx.x;
    const int lane = tid & 31;
    const int wid  = tid >> 5;
    const int wm   = wid & 3;
    const int wn   = wid >> 2;
    const int lr   = lane >> 2;
    const int lc   = lane & 3;
    const int lt   = lane >> 3;
    const int lrw  = lane & 7;

    const int m0 = blockIdx.y * BM;
    const int n0 = blockIdx.x * BN;

    float acc[2][4][4];
#pragma unroll
    for (int mt = 0; mt < 2; mt++)
#pragma unroll
        for (int nt = 0; nt < 4; nt++)
#pragma unroll
            for (int j = 0; j < 4; j++) acc[mt][nt][j] = 0.f;

    const int Kt = Kp / 16;

    auto prefetch = [&](int kt, int s) {
        const int k0p = kt * 16;
        const uint32_t base = sm_u32 + s * G_STAGE * 4;
#pragma unroll
        for (int j = 0; j < 2; j++) {
            const int idx = tid + 256 * j;
            const int row = idx >> 2, ch = idx & 3;
            cp16(base + (row * SA_STRIDE + ch * 4) * 4,
                 &Ahi[(size_t)(m0 + row) * Kp + k0p + ch * 4]);
            cp16(base + (2560 + row * SA_STRIDE + ch * 4) * 4,
                 &Alo[(size_t)(m0 + row) * Kp + k0p + ch * 4]);
        }
        {
            const int row = tid >> 2, ch = tid & 3;
            cp16(base + (5120 + row * SB_STRIDE + ch * 4) * 4,
                 &Bthi[(size_t)(n0 + row) * Kp + k0p + ch * 4]);
            cp16(base + (6400 + row * SB_STRIDE + ch * 4) * 4,
                 &Btlo[(size_t)(n0 + row) * Kp + k0p + ch * 4]);
        }
    };

    prefetch(0, 0);
    CP_COMMIT();

    for (int kt = 0; kt < Kt; kt++) {
        if (kt + 1 < Kt) {
            prefetch(kt + 1, (kt + 1) & 1);
            CP_COMMIT();
            CP_WAIT_1();
        } else {
            CP_WAIT_0();
        }
        __syncthreads();

        const uint32_t sbase = sm_u32 + (kt & 1) * G_STAGE * 4;

#pragma unroll
        for (int ks = 0; ks < 2; ks++) {
            uint32_t ahi[2][4], alo[2][4];
#pragma unroll
            for (int mt = 0; mt < 2; mt++) {
                const int m = wm * 32 + mt * 16 + (lt & 1) * 8 + lrw;
                const uint32_t off = (uint32_t)(m * SA_STRIDE + ks * 8 + (lt >> 1) * 4) * 4;
                ldm_x4(ahi[mt], sbase + off);
                ldm_x4(alo[mt], sbase + 2560 * 4 + off);
            }
#pragma unroll
            for (int ntp = 0; ntp < 2; ntp++) {
                const int n = wn * 32 + ntp * 16 + (lt >> 1) * 8 + lrw;
                const uint32_t off = (uint32_t)(n * SB_STRIDE + ks * 8 + (lt & 1) * 4) * 4;
                uint32_t th[4], tl[4];
                ldm_x4(th, sbase + 5120 * 4 + off);
                ldm_x4(tl, sbase + 6400 * 4 + off);
                uint32_t bh0[2] = {th[0], th[1]}, bh1[2] = {th[2], th[3]};
                uint32_t bl0[2] = {tl[0], tl[1]}, bl1[2] = {tl[2], tl[3]};
#pragma unroll
                for (int mt = 0; mt < 2; mt++) {
                    mma_bf16(acc[mt][2 * ntp],     ahi[mt], bh0);
                    mma_bf16(acc[mt][2 * ntp],     ahi[mt], bl0);
                    mma_bf16(acc[mt][2 * ntp],     alo[mt], bh0);
                    mma_bf16(acc[mt][2 * ntp + 1], ahi[mt], bh1);
                    mma_bf16(acc[mt][2 * ntp + 1], ahi[mt], bl1);
                    mma_bf16(acc[mt][2 * ntp + 1], alo[mt], bh1);
                }
            }
        }
        __syncthreads();
    }

#pragma unroll
    for (int mt = 0; mt < 2; mt++) {
#pragma unroll
        for (int nt = 0; nt < 4; nt++) {
            const int row0 = m0 + wm * 32 + mt * 16 + lr;
            const int col  = n0 + wn * 32 + nt * 8 + lc * 2;
            float2 v0 = make_float2(acc[mt][nt][0], acc[mt][nt][1]);
            float2 v1 = make_float2(acc[mt][nt][2], acc[mt][nt][3]);
            *reinterpret_cast<float2*>(&C[(size_t)row0 * N + col]) = v0;
            *reinterpret_cast<float2*>(&C[(size_t)(row0 + 8) * N + col]) = v1;
        }
    }
}

// ===========================================================================
// prep_qkv: merged rope_conv + vtrans_conv (one launch).
// Blocks [0, 8192): RoPE q (scaled, fp16 hi/lo) + k (fp16 single).
// Blocks [8192, 9216): V transpose -> fp16x2 [b,h,d,t].
// Both paths byte-identical memory behaviour to the R13 kernels.
// ===========================================================================
__global__ __launch_bounds__(256) void prep_qkv(const float* __restrict__ sin_t,
                                                const float* __restrict__ cos_t) {
    __shared__ float vs[64][65];
    const int bx = blockIdx.x;
    const int tid = threadIdx.x;

    if (bx < 8192) {
        const int idx = bx * 256 + tid;
        const int i = idx & 31;
        const int h = (idx >> 5) & (NH_ - 1);
        const int bt = idx >> 9;
        const int t = bt & (T_ - 1);
        const int b = bt >> 11;

        const float s = sin_t[t * HD_ + 2 * i];
        const float c = cos_t[t * HD_ + 2 * i];

        const float* row = g_qkv + (size_t)bt * (3 * DIM_);
        const size_t o = ((size_t)(b * NH_ + h) * T_ + t) * 32 + i;

        float2 q = *reinterpret_cast<const float2*>(row + h * HD_ + 2 * i);
        float q0 = (q.x * c - q.y * s) * 0.125f;
        float q1 = (q.y * c + q.x * s) * 0.125f;
        g_qhi[o] = pack_h2f(q0, q1);
        g_qlo[o] = pack_l2f(q0, q1);

        float2 k = *reinterpret_cast<const float2*>(row + DIM_ + h * HD_ + 2 * i);
        float k0 = k.x * c - k.y * s;
        float k1 = k.y * c + k.x * s;
        g_kh[o] = pack_h2f(k0, k1);
    } else {
        const int bx2 = bx - 8192;
        const int t0 = (bx2 & 31) * 64;
        const int h  = (bx2 >> 5) & (NH_ - 1);
        const int b  = bx2 >> 9;

        const int r = tid >> 2;
        const int q = (tid & 3) * 16;
        const float* src = g_qkv + (size_t)(b * T_ + t0 + r) * (3 * DIM_)
                           + 2 * DIM_ + h * HD_;
#pragma unroll
        for (int v = 0; v < 4; v++) {
            float4 f4 = *reinterpret_cast<const float4*>(src + q + v * 4);
            vs[r][q + v * 4 + 0] = f4.x;
            vs[r][q + v * 4 + 1] = f4.y;
            vs[r][q + v * 4 + 2] = f4.z;
            vs[r][q + v * 4 + 3] = f4.w;
        }
        __syncthreads();

        const int Tp = T_ / 2;
#pragma unroll
        for (int j = 0; j < 8; j++) {
            const int c = tid + 256 * j;
            const int d = c >> 5, p = c & 31;
            float f0 = vs[2 * p][d], f1 = vs[2 * p + 1][d];
            const size_t o = ((size_t)(b * NH_ + h) * HD_ + d) * Tp + (t0 >> 1) + p;
            g_vt[o] = pack_h2f(f0, f1);
        }
    }
}

// ===========================================================================
// Flash attention (exact R13): BQ=128, all-fp16 MMAs.
// S = (Qhi + Qlo) @ K^T : 2 MMAs. PV: P hi/lo @ V : 2 MMAs.
// smem (uint32): Q hi/lo [0..9216); stages at 9216 + s*4608:
//   K[0..2304) V[2304..4608)
// ===========================================================================
#define FS 36
#define F_STAGE 4608
#define FA_SMEM_BYTES ((9216 + 2 * F_STAGE) * 4)   // 73,728

__global__ __launch_bounds__(256, 2) void flash_mma(uint32_t* __restrict__ yhi,
                                                    uint32_t* __restrict__ ylo) {
    extern __shared__ uint32_t sm[];
    const uint32_t sm_u32 = (uint32_t)__cvta_generic_to_shared(sm);
    uint32_t* Qhi = sm;
    uint32_t* Qlo = Qhi + 128 * FS;

    const int tid  = threadIdx.x;
    const int lane = tid & 31;
    const int wid  = tid >> 5;
    const int lr   = lane >> 2;
    const int lc   = lane & 3;
    const int lt   = lane >> 3;
    const int lrw  = lane & 7;

    const int qt = (T_ / 128 - 1) - blockIdx.x;
    const int h  = blockIdx.y;
    const int b  = blockIdx.z;
    const int q0 = qt * 128;
    const size_t hb = (size_t)(b * NH_ + h);
    const int Tp = T_ / 2;

#pragma unroll
    for (int j = 0; j < 8; j++) {
        const int c = tid + 256 * j;
        const int row = c >> 4, cc = c & 15;
        uint2 vh = *reinterpret_cast<const uint2*>(
            &g_qhi[(hb * T_ + q0 + row) * 32 + cc * 2]);
        uint2 vl = *reinterpret_cast<const uint2*>(
            &g_qlo[(hb * T_ + q0 + row) * 32 + cc * 2]);
        *reinterpret_cast<uint2*>(&Qhi[row * FS + cc * 2]) = vh;
        *reinterpret_cast<uint2*>(&Qlo[row * FS + cc * 2]) = vl;
    }

    auto prefetch_kv = [&](int kt, int s) {
        const uint32_t base = sm_u32 + (9216 + s * F_STAGE) * 4;
#pragma unroll
        for (int j = 0; j < 2; j++) {
            const int idx = tid + 256 * j;
            const int row = idx >> 3, ch = idx & 7;
            const uint32_t soff = (row * FS + ch * 4) * 4;
            cp16(base + soff,
                 &g_kh[(hb * T_ + kt * 64 + row) * 32 + ch * 4]);
            cp16(base + 2304 * 4 + soff,
                 &g_vt[(hb * HD_ + row) * Tp + kt * 32 + ch * 4]);
        }
    };

    float O[8][4];
#pragma unroll
    for (int nt = 0; nt < 8; nt++)
#pragma unroll
        for (int j = 0; j < 4; j++) O[nt][j] = 0.f;
    float m0 = -INFINITY, m1 = -INFINITY, l0 = 0.f, l1 = 0.f;

    const int kt_max = 2 * qt + 1;

    prefetch_kv(0, 0);
    CP_COMMIT();

    const int qm = wid * 16 + (lt & 1) * 8 + lrw;
    const int nrow_base = (lt >> 1) * 8 + lrw;

    for (int kt = 0; kt <= kt_max; kt++) {
        if (kt < kt_max) {
            prefetch_kv(kt + 1, (kt + 1) & 1);
            CP_COMMIT();
            CP_WAIT_1();
        } else {
            CP_WAIT_0();
        }
        __syncthreads();

        const uint32_t kbase = sm_u32 + (9216 + (kt & 1) * F_STAGE) * 4;

        const int rel = kt * 64 - q0;
        if (rel <= wid * 16 + 15) {
            float sf[8][4];
#pragma unroll
            for (int nt = 0; nt < 8; nt++)
#pragma unroll
                for (int j = 0; j < 4; j++) sf[nt][j] = 0.f;

#pragma unroll
            for (int ks = 0; ks < 4; ks++) {
                const uint32_t qoff = (uint32_t)(qm * FS + ks * 8 + (lt >> 1) * 4) * 4;
                uint32_t ahi[4], alo[4];
                ldm_x4(ahi, sm_u32 + qoff);
                ldm_x4(alo, sm_u32 + 4608 * 4 + qoff);
#pragma unroll
                for (int ntp = 0; ntp < 4; ntp++) {
                    const int n = ntp * 16 + nrow_base;
                    const uint32_t koff = (uint32_t)(n * FS + ks * 8 + (lt & 1) * 4) * 4;
                    uint32_t th[4];
                    ldm_x4(th, kbase + koff);
                    uint32_t bh0[2] = {th[0], th[1]}, bh1[2] = {th[2], th[3]};
                    mma_fp16(sf[2 * ntp],     ahi, bh0);
                    mma_fp16(sf[2 * ntp],     alo, bh0);
                    mma_fp16(sf[2 * ntp + 1], ahi, bh1);
                    mma_fp16(sf[2 * ntp + 1], alo, bh1);
                }
            }

            if (rel + 63 > wid * 16) {
                const int r0 = wid * 16 + lr;
#pragma unroll
                for (int nt = 0; nt < 8; nt++) {
                    const int c0 = rel + nt * 8 + 2 * lc;
                    if (c0 > r0)         sf[nt][0] = -INFINITY;
                    if (c0 + 1 > r0)     sf[nt][1] = -INFINITY;
                    if (c0 > r0 + 8)     sf[nt][2] = -INFINITY;
                    if (c0 + 1 > r0 + 8) sf[nt][3] = -INFINITY;
                }
            }

            float ml0 = -INFINITY, ml1 = -INFINITY;
#pragma unroll
            for (int nt = 0; nt < 8; nt++) {
                ml0 = fmaxf(ml0, fmaxf(sf[nt][0], sf[nt][1]));
                ml1 = fmaxf(ml1, fmaxf(sf[nt][2], sf[nt][3]));
            }
            ml0 = fmaxf(ml0, __shfl_xor_sync(0xffffffffu, ml0, 1));
            ml0 = fmaxf(ml0, __shfl_xor_sync(0xffffffffu, ml0, 2));
            ml1 = fmaxf(ml1, __shfl_xor_sync(0xffffffffu, ml1, 1));
            ml1 = fmaxf(ml1, __shfl_xor_sync(0xffffffffu, ml1, 2));

            const float mn0 = fmaxf(m0, ml0);
            const float mn1 = fmaxf(m1, ml1);
            const float al0 = __expf(m0 - mn0);
            const float al1 = __expf(m1 - mn1);

            float rs0 = 0.f, rs1 = 0.f;
#pragma unroll
            for (int nt = 0; nt < 8; nt++) {
                sf[nt][0] = __expf(sf[nt][0] - mn0);
                sf[nt][1] = __expf(sf[nt][1] - mn0);
                sf[nt][2] = __expf(sf[nt][2] - mn1);
                sf[nt][3] = __expf(sf[nt][3] - mn1);
                rs0 += sf[nt][0] + sf[nt][1];
                rs1 += sf[nt][2] + sf[nt][3];
            }
            rs0 += __shfl_xor_sync(0xffffffffu, rs0, 1);
            rs0 += __shfl_xor_sync(0xffffffffu, rs0, 2);
            rs1 += __shfl_xor_sync(0xffffffffu, rs1, 1);
            rs1 += __shfl_xor_sync(0xffffffffu, rs1, 2);

            l0 = l0 * al0 + rs0;
            l1 = l1 * al1 + rs1;
            m0 = mn0; m1 = mn1;
#pragma unroll
            for (int nt = 0; nt < 8; nt++) {
                O[nt][0] *= al0; O[nt][1] *= al0;
                O[nt][2] *= al1; O[nt][3] *= al1;
            }

#pragma unroll
            for (int ks = 0; ks < 4; ks++) {
                uint32_t ph[4], pl[4];
                ph[0] = pack_h2f(sf[2 * ks][0],     sf[2 * ks][1]);
                ph[1] = pack_h2f(sf[2 * ks][2],     sf[2 * ks][3]);
                ph[2] = pack_h2f(sf[2 * ks + 1][0], sf[2 * ks + 1][1]);
                ph[3] = pack_h2f(sf[2 * ks + 1][2], sf[2 * ks + 1][3]);
                pl[0] = pack_l2f(sf[2 * ks][0],     sf[2 * ks][1]);
                pl[1] = pack_l2f(sf[2 * ks][2],     sf[2 * ks][3]);
                pl[2] = pack_l2f(sf[2 * ks + 1][0], sf[2 * ks + 1][1]);
                pl[3] = pack_l2f(sf[2 * ks + 1][2], sf[2 * ks + 1][3]);
#pragma unroll
                for (int ntp = 0; ntp < 4; ntp++) {
                    const int n = ntp * 16 + nrow_base;
                    const uint32_t voff = (uint32_t)(n * FS + ks * 8 + (lt & 1) * 4) * 4;
                    uint32_t tv[4];
                    ldm_x4(tv, kbase + 2304 * 4 + voff);
                    uint32_t v0[2] = {tv[0], tv[1]}, v1[2] = {tv[2], tv[3]};
                    mma_fp16(O[2 * ntp],     ph, v0);
                    mma_fp16(O[2 * ntp],     pl, v0);
                    mma_fp16(O[2 * ntp + 1], ph, v1);
                    mma_fp16(O[2 * ntp + 1], pl, v1);
                }
            }
        }
        __syncthreads();
    }

    const float inv0 = 1.0f / l0;
    const float inv1 = 1.0f / l1;
    const int r0 = q0 + wid * 16 + lr;
#pragma unroll
    for (int nt = 0; nt < 8; nt++) {
        const int pcol = h * 32 + nt * 4 + lc;
        float a = O[nt][0] * inv0, bb = O[nt][1] * inv0;
        float ccv = O[nt][2] * inv1, d = O[nt][3] * inv1;
        yhi[(size_t)(b * T_ + r0) * 512 + pcol]     = pack_hi2(a, bb);
        ylo[(size_t)(b * T_ + r0) * 512 + pcol]     = pack_lo2(a, bb);
        yhi[(size_t)(b * T_ + r0 + 8) * 512 + pcol] = pack_hi2(ccv, d);
        ylo[(size_t)(b * T_ + r0 + 8) * 512 + pcol] = pack_lo2(ccv, d);
    }
}

// ---------------------------------------------------------------------------
// Launch (single stream)
// ---------------------------------------------------------------------------
extern "C" void kernel_launch(void* const* d_in, const int* in_sizes, int n_in,
                              void* d_out, int out_size) {
    const float* x      = (const float*)d_in[0];
    const float* sin_t  = (const float*)d_in[1];
    const float* cos_t  = (const float*)d_in[2];
    const float* W_qkv  = (const float*)d_in[3];
    const float* W_proj = (const float*)d_in[4];
    float* out = (float*)d_out;

    float* qkv_ptr = nullptr;
    uint32_t *ahi, *alo, *wthi, *wtlo;
    cudaGetSymbolAddress((void**)&qkv_ptr, g_qkv);
    cudaGetSymbolAddress((void**)&ahi, g_ahi);
    cudaGetSymbolAddress((void**)&alo, g_alo);
    cudaGetSymbolAddress((void**)&wthi, g_wthi);
    cudaGetSymbolAddress((void**)&wtlo, g_wtlo);

    const int M = B_ * T_;
    const int Kp = DIM_ / 2;

    cudaFuncSetAttribute(gemm_pre, cudaFuncAttributeMaxDynamicSharedMemorySize,
                         GEMM_SMEM_BYTES);
    cudaFuncSetAttribute(flash_mma, cudaFuncAttributeMaxDynamicSharedMemorySize,
                         FA_SMEM_BYTES);

    // 1) split x; transpose+split W_qkv; QKV GEMM
    conv_rows<<<(M * Kp) / 256, 256>>>(x, ahi, alo, M * Kp);
    {
        dim3 g(3 * DIM_ / 32, DIM_ / 32);
        conv_tr<<<g, 256>>>(W_qkv, wthi, wtlo, DIM_, 3 * DIM_);
    }
    {
        dim3 g((3 * DIM_) / BN, M / BM);
        gemm_pre<<<g, 256, GEMM_SMEM_BYTES>>>(ahi, alo, wthi, wtlo, qkv_ptr,
                                              M, 3 * DIM_, Kp);
    }

    // 2) merged RoPE(q,k) + V-transpose prepass
    prep_qkv<<<9216, 256>>>(sin_t, cos_t);

    // 3) Flash attention (writes bf16 split output into g_ahi/g_alo)
    {
        dim3 g(T_ / 128, NH_, B_);
        flash_mma<<<g, 256, FA_SMEM_BYTES>>>(ahi, alo);
    }

    // 4) transpose+split W_proj; output projection
    {
        dim3 g(DIM_ / 32, DIM_ / 32);
        conv_tr<<<g, 256>>>(W_proj, wthi, wtlo, DIM_, DIM_);
    }
    {
        dim3 g(DIM_ / BN, M / BM);
        gemm_pre<<<g, 256, GEMM_SMEM_BYTES>>>(ahi, alo, wthi, wtlo, out,
                                              M, DIM_, Kp);
    }
}

// round 16
// speedup vs baseline: 1.3919x; 1.1026x over previous
#include <cuda_runtime.h>
#include <cuda_bf16.h>
#include <cuda_fp16.h>
#include <math.h>
#include <stdint.h>

#define B_   2
#define T_   2048
#define DIM_ 1024
#define NH_  16
#define HD_  64

// fp32 scratch
__device__ float g_qkv[(size_t)B_ * T_ * 3 * DIM_];

// packed scratch
__device__ uint32_t g_ahi[(size_t)4096 * 512];                 // bf16 hi pairs
__device__ uint32_t g_alo[(size_t)4096 * 512];                 // bf16 lo pairs
__device__ uint32_t g_wthi[(size_t)3072 * 512];
__device__ uint32_t g_wtlo[(size_t)3072 * 512];
__device__ uint32_t g_qh [(size_t)B_ * NH_ * T_ * 32];         // fp16 single (scaled q)
__device__ uint32_t g_kh [(size_t)B_ * NH_ * T_ * 32];         // fp16 single (k)
__device__ uint32_t g_vt [(size_t)B_ * NH_ * HD_ * (T_ / 2)];  // fp16x2 transposed v

__device__ __forceinline__ void mma_bf16(float c[4], const uint32_t a[4],
                                         const uint32_t b[2]) {
    asm volatile(
        "mma.sync.aligned.m16n8k16.row.col.f32.bf16.bf16.f32 "
        "{%0,%1,%2,%3}, {%4,%5,%6,%7}, {%8,%9}, {%0,%1,%2,%3};\n"
        : "+f"(c[0]), "+f"(c[1]), "+f"(c[2]), "+f"(c[3])
        : "r"(a[0]), "r"(a[1]), "r"(a[2]), "r"(a[3]), "r"(b[0]), "r"(b[1]));
}

__device__ __forceinline__ void mma_fp16(float c[4], const uint32_t a[4],
                                         const uint32_t b[2]) {
    asm volatile(
        "mma.sync.aligned.m16n8k16.row.col.f32.f16.f16.f32 "
        "{%0,%1,%2,%3}, {%4,%5,%6,%7}, {%8,%9}, {%0,%1,%2,%3};\n"
        : "+f"(c[0]), "+f"(c[1]), "+f"(c[2]), "+f"(c[3])
        : "r"(a[0]), "r"(a[1]), "r"(a[2]), "r"(a[3]), "r"(b[0]), "r"(b[1]));
}

__device__ __forceinline__ void ldm_x4(uint32_t r[4], uint32_t addr) {
    asm volatile("ldmatrix.sync.aligned.m8n8.x4.shared.b16 {%0,%1,%2,%3}, [%4];\n"
                 : "=r"(r[0]), "=r"(r[1]), "=r"(r[2]), "=r"(r[3])
                 : "r"(addr));
}

__device__ __forceinline__ uint32_t pack_hi2(float x, float y) {
    __nv_bfloat162 p = {__float2bfloat16_rn(x), __float2bfloat16_rn(y)};
    return *reinterpret_cast<uint32_t*>(&p);
}
__device__ __forceinline__ uint32_t pack_lo2(float x, float y) {
    float xh = __bfloat162float(__float2bfloat16_rn(x));
    float yh = __bfloat162float(__float2bfloat16_rn(y));
    __nv_bfloat162 p = {__float2bfloat16_rn(x - xh), __float2bfloat16_rn(y - yh)};
    return *reinterpret_cast<uint32_t*>(&p);
}
__device__ __forceinline__ uint32_t pack_h2f(float x, float y) {
    __half2 p = __floats2half2_rn(x, y);
    return *reinterpret_cast<uint32_t*>(&p);
}

__device__ __forceinline__ void cp16(uint32_t dst_smem, const void* src) {
    asm volatile("cp.async.cg.shared.global [%0], [%1], 16;\n"
                 :: "r"(dst_smem), "l"(src));
}
#define CP_COMMIT() asm volatile("cp.async.commit_group;\n" ::: "memory")
#define CP_WAIT_1() asm volatile("cp.async.wait_group 1;\n" ::: "memory")
#define CP_WAIT_0() asm volatile("cp.async.wait_group 0;\n" ::: "memory")

// ===========================================================================
// conv_rows: fp32 [M][K] -> hi/lo bf16-pair [M][K/2]
// ===========================================================================
__global__ __launch_bounds__(256) void conv_rows(const float* __restrict__ src,
                                                 uint32_t* __restrict__ hi,
                                                 uint32_t* __restrict__ lo,
                                                 int npairs) {
    const int i = blockIdx.x * blockDim.x + threadIdx.x;
    if (i >= npairs) return;
    float2 f = *reinterpret_cast<const float2*>(src + (size_t)i * 2);
    hi[i] = pack_hi2(f.x, f.y);
    lo[i] = pack_lo2(f.x, f.y);
}

// ===========================================================================
// conv_tr: fp32 W[K][N] -> transposed hi/lo bf16 pairs [N][K/2]
// ===========================================================================
__global__ __launch_bounds__(256) void conv_tr(const float* __restrict__ src,
                                               uint32_t* __restrict__ hi,
                                               uint32_t* __restrict__ lo,
                                               int K, int N) {
    __shared__ float vs[32][33];
    const int tid = threadIdx.x;
    const int n0 = blockIdx.x * 32;
    const int k0 = blockIdx.y * 32;
    const int Kp = K >> 1;
#pragma unroll
    for (int e = 0; e < 4; e++) {
        const int idx = tid + 256 * e;
        const int kl = idx >> 5, nl = idx & 31;
        vs[kl][nl] = src[(size_t)(k0 + kl) * N + n0 + nl];
    }
    __syncthreads();
#pragma unroll
    for (int e = 0; e < 2; e++) {
        const int idx = tid + 256 * e;
        const int nl = idx >> 4, p = idx & 15;
        float f0 = vs[2 * p][nl], f1 = vs[2 * p + 1][nl];
        const size_t o = (size_t)(n0 + nl) * Kp + (k0 >> 1) + p;
        hi[o] = pack_hi2(f0, f1);
        lo[o] = pack_lo2(f0, f1);
    }
}

// ===========================================================================
// gemm_pre (bf16x3, unchanged): BM=128 BN=64, 2-stage cp.async, ldmatrix.
// ===========================================================================
#define BM 128
#define BN 64
#define SA_STRIDE 20
#define SB_STRIDE 20
#define G_STAGE 7680
#define GEMM_SMEM_BYTES (2 * G_STAGE * 4)

__global__ __launch_bounds__(256) void gemm_pre(const uint32_t* __restrict__ Ahi,
                                                const uint32_t* __restrict__ Alo,
                                                const uint32_t* __restrict__ Bthi,
                                                const uint32_t* __restrict__ Btlo,
                                                float* __restrict__ C,
                                                int M, int N, int Kp) {
    extern __shared__ uint32_t sm[];
    const uint32_t sm_u32 = (uint32_t)__cvta_generic_to_shared(sm);

    const int tid  = threadIdx.x;
    const int lane = tid & 31;
    const int wid  = tid >> 5;
    const int wm   = wid & 3;
    const int wn   = wid >> 2;
    const int lr   = lane >> 2;
    const int lc   = lane & 3;
    const int lt   = lane >> 3;
    const int lrw  = lane & 7;

    const int m0 = blockIdx.y * BM;
    const int n0 = blockIdx.x * BN;

    float acc[2][4][4];
#pragma unroll
    for (int mt = 0; mt < 2; mt++)
#pragma unroll
        for (int nt = 0; nt < 4; nt++)
#pragma unroll
            for (int j = 0; j < 4; j++) acc[mt][nt][j] = 0.f;

    const int Kt = Kp / 16;

    auto prefetch = [&](int kt, int s) {
        const int k0p = kt * 16;
        const uint32_t base = sm_u32 + s * G_STAGE * 4;
#pragma unroll
        for (int j = 0; j < 2; j++) {
            const int idx = tid + 256 * j;
            const int row = idx >> 2, ch = idx & 3;
            cp16(base + (row * SA_STRIDE + ch * 4) * 4,
                 &Ahi[(size_t)(m0 + row) * Kp + k0p + ch * 4]);
            cp16(base + (2560 + row * SA_STRIDE + ch * 4) * 4,
                 &Alo[(size_t)(m0 + row) * Kp + k0p + ch * 4]);
        }
        {
            const int row = tid >> 2, ch = tid & 3;
            cp16(base + (5120 + row * SB_STRIDE + ch * 4) * 4,
                 &Bthi[(size_t)(n0 + row) * Kp + k0p + ch * 4]);
            cp16(base + (6400 + row * SB_STRIDE + ch * 4) * 4,
                 &Btlo[(size_t)(n0 + row) * Kp + k0p + ch * 4]);
        }
    };

    prefetch(0, 0);
    CP_COMMIT();

    for (int kt = 0; kt < Kt; kt++) {
        if (kt + 1 < Kt) {
            prefetch(kt + 1, (kt + 1) & 1);
            CP_COMMIT();
            CP_WAIT_1();
        } else {
            CP_WAIT_0();
        }
        __syncthreads();

        const uint32_t sbase = sm_u32 + (kt & 1) * G_STAGE * 4;

#pragma unroll
        for (int ks = 0; ks < 2; ks++) {
            uint32_t ahi[2][4], alo[2][4];
#pragma unroll
            for (int mt = 0; mt < 2; mt++) {
                const int m = wm * 32 + mt * 16 + (lt & 1) * 8 + lrw;
                const uint32_t off = (uint32_t)(m * SA_STRIDE + ks * 8 + (lt >> 1) * 4) * 4;
                ldm_x4(ahi[mt], sbase + off);
                ldm_x4(alo[mt], sbase + 2560 * 4 + off);
            }
#pragma unroll
            for (int ntp = 0; ntp < 2; ntp++) {
                const int n = wn * 32 + ntp * 16 + (lt >> 1) * 8 + lrw;
                const uint32_t off = (uint32_t)(n * SB_STRIDE + ks * 8 + (lt & 1) * 4) * 4;
                uint32_t th[4], tl[4];
                ldm_x4(th, sbase + 5120 * 4 + off);
                ldm_x4(tl, sbase + 6400 * 4 + off);
                uint32_t bh0[2] = {th[0], th[1]}, bh1[2] = {th[2], th[3]};
                uint32_t bl0[2] = {tl[0], tl[1]}, bl1[2] = {tl[2], tl[3]};
#pragma unroll
                for (int mt = 0; mt < 2; mt++) {
                    mma_bf16(acc[mt][2 * ntp],     ahi[mt], bh0);
                    mma_bf16(acc[mt][2 * ntp],     ahi[mt], bl0);
                    mma_bf16(acc[mt][2 * ntp],     alo[mt], bh0);
                    mma_bf16(acc[mt][2 * ntp + 1], ahi[mt], bh1);
                    mma_bf16(acc[mt][2 * ntp + 1], ahi[mt], bl1);
                    mma_bf16(acc[mt][2 * ntp + 1], alo[mt], bh1);
                }
            }
        }
        __syncthreads();
    }

#pragma unroll
    for (int mt = 0; mt < 2; mt++) {
#pragma unroll
        for (int nt = 0; nt < 4; nt++) {
            const int row0 = m0 + wm * 32 + mt * 16 + lr;
            const int col  = n0 + wn * 32 + nt * 8 + lc * 2;
            float2 v0 = make_float2(acc[mt][nt][0], acc[mt][nt][1]);
            float2 v1 = make_float2(acc[mt][nt][2], acc[mt][nt][3]);
            *reinterpret_cast<float2*>(&C[(size_t)row0 * N + col]) = v0;
            *reinterpret_cast<float2*>(&C[(size_t)(row0 + 8) * N + col]) = v1;
        }
    }
}

// ===========================================================================
// prep_qkv: merged RoPE(q,k) + V-transpose.
// Blocks [0, 8192): q scaled -> fp16 single; k -> fp16 single.
// Blocks [8192, 9216): V transpose -> fp16x2 [b,h,d,t].
// ===========================================================================
__global__ __launch_bounds__(256) void prep_qkv(const float* __restrict__ sin_t,
                                                const float* __restrict__ cos_t) {
    __shared__ float vs[64][65];
    const int bx = blockIdx.x;
    const int tid = threadIdx.x;

    if (bx < 8192) {
        const int idx = bx * 256 + tid;
        const int i = idx & 31;
        const int h = (idx >> 5) & (NH_ - 1);
        const int bt = idx >> 9;
        const int t = bt & (T_ - 1);
        const int b = bt >> 11;

        const float s = sin_t[t * HD_ + 2 * i];
        const float c = cos_t[t * HD_ + 2 * i];

        const float* row = g_qkv + (size_t)bt * (3 * DIM_);
        const size_t o = ((size_t)(b * NH_ + h) * T_ + t) * 32 + i;

        float2 q = *reinterpret_cast<const float2*>(row + h * HD_ + 2 * i);
        float q0 = (q.x * c - q.y * s) * 0.125f;
        float q1 = (q.y * c + q.x * s) * 0.125f;
        g_qh[o] = pack_h2f(q0, q1);

        float2 k = *reinterpret_cast<const float2*>(row + DIM_ + h * HD_ + 2 * i);
        float k0 = k.x * c - k.y * s;
        float k1 = k.y * c + k.x * s;
        g_kh[o] = pack_h2f(k0, k1);
    } else {
        const int bx2 = bx - 8192;
        const int t0 = (bx2 & 31) * 64;
        const int h  = (bx2 >> 5) & (NH_ - 1);
        const int b  = bx2 >> 9;

        const int r = tid >> 2;
        const int q = (tid & 3) * 16;
        const float* src = g_qkv + (size_t)(b * T_ + t0 + r) * (3 * DIM_)
                           + 2 * DIM_ + h * HD_;
#pragma unroll
        for (int v = 0; v < 4; v++) {
            float4 f4 = *reinterpret_cast<const float4*>(src + q + v * 4);
            vs[r][q + v * 4 + 0] = f4.x;
            vs[r][q + v * 4 + 1] = f4.y;
            vs[r][q + v * 4 + 2] = f4.z;
            vs[r][q + v * 4 + 3] = f4.w;
        }
        __syncthreads();

        const int Tp = T_ / 2;
#pragma unroll
        for (int j = 0; j < 8; j++) {
            const int c = tid + 256 * j;
            const int d = c >> 5, p = c & 31;
            float f0 = vs[2 * p][d], f1 = vs[2 * p + 1][d];
            const size_t o = ((size_t)(b * NH_ + h) * HD_ + d) * Tp + (t0 >> 1) + p;
            g_vt[o] = pack_h2f(f0, f1);
        }
    }
}

// ===========================================================================
// Flash attention: BQ=128, single-fp16 Q/K/V/P (4 MMAs per warp-tile pair).
// smem (uint32): Q [0..4608); stages at 4608 + s*4608: K[0..2304) V[2304..4608)
// ===========================================================================
#define FS 36
#define F_STAGE 4608
#define FA_SMEM_BYTES (3 * 4608 * 4)   // 55,296

__global__ __launch_bounds__(256, 2) void flash_mma(uint32_t* __restrict__ yhi,
                                                    uint32_t* __restrict__ ylo) {
    extern __shared__ uint32_t sm[];
    const uint32_t sm_u32 = (uint32_t)__cvta_generic_to_shared(sm);
    uint32_t* Qh = sm;

    const int tid  = threadIdx.x;
    const int lane = tid & 31;
    const int wid  = tid >> 5;
    const int lr   = lane >> 2;
    const int lc   = lane & 3;
    const int lt   = lane >> 3;
    const int lrw  = lane & 7;

    const int qt = (T_ / 128 - 1) - blockIdx.x;
    const int h  = blockIdx.y;
    const int b  = blockIdx.z;
    const int q0 = qt * 128;
    const size_t hb = (size_t)(b * NH_ + h);
    const int Tp = T_ / 2;

#pragma unroll
    for (int j = 0; j < 4; j++) {
        const int c = tid + 256 * j;
        const int row = c >> 3, cc = c & 7;
        uint4 vh = *reinterpret_cast<const uint4*>(
            &g_qh[(hb * T_ + q0 + row) * 32 + cc * 4]);
        *reinterpret_cast<uint4*>(&Qh[row * FS + cc * 4]) = vh;
    }

    auto prefetch_kv = [&](int kt, int s) {
        const uint32_t base = sm_u32 + (4608 + s * F_STAGE) * 4;
#pragma unroll
        for (int j = 0; j < 2; j++) {
            const int idx = tid + 256 * j;
            const int row = idx >> 3, ch = idx & 7;
            const uint32_t soff = (row * FS + ch * 4) * 4;
            cp16(base + soff,
                 &g_kh[(hb * T_ + kt * 64 + row) * 32 + ch * 4]);
            cp16(base + 2304 * 4 + soff,
                 &g_vt[(hb * HD_ + row) * Tp + kt * 32 + ch * 4]);
        }
    };

    float O[8][4];
#pragma unroll
    for (int nt = 0; nt < 8; nt++)
#pragma unroll
        for (int j = 0; j < 4; j++) O[nt][j] = 0.f;
    float m0 = -INFINITY, m1 = -INFINITY, l0 = 0.f, l1 = 0.f;

    const int kt_max = 2 * qt + 1;

    prefetch_kv(0, 0);
    CP_COMMIT();

    const int qm = wid * 16 + (lt & 1) * 8 + lrw;
    const int nrow_base = (lt >> 1) * 8 + lrw;

    for (int kt = 0; kt <= kt_max; kt++) {
        if (kt < kt_max) {
            prefetch_kv(kt + 1, (kt + 1) & 1);
            CP_COMMIT();
            CP_WAIT_1();
        } else {
            CP_WAIT_0();
        }
        __syncthreads();

        const uint32_t kbase = sm_u32 + (4608 + (kt & 1) * F_STAGE) * 4;

        const int rel = kt * 64 - q0;
        if (rel <= wid * 16 + 15) {
            // ---- S = Q @ K^T (single fp16) ----
            float sf[8][4];
#pragma unroll
            for (int nt = 0; nt < 8; nt++)
#pragma unroll
                for (int j = 0; j < 4; j++) sf[nt][j] = 0.f;

#pragma unroll
            for (int ks = 0; ks < 4; ks++) {
                const uint32_t qoff = (uint32_t)(qm * FS + ks * 8 + (lt >> 1) * 4) * 4;
                uint32_t aq[4];
                ldm_x4(aq, sm_u32 + qoff);
#pragma unroll
                for (int ntp = 0; ntp < 4; ntp++) {
                    const int n = ntp * 16 + nrow_base;
                    const uint32_t koff = (uint32_t)(n * FS + ks * 8 + (lt & 1) * 4) * 4;
                    uint32_t th[4];
                    ldm_x4(th, kbase + koff);
                    uint32_t bh0[2] = {th[0], th[1]}, bh1[2] = {th[2], th[3]};
                    mma_fp16(sf[2 * ntp],     aq, bh0);
                    mma_fp16(sf[2 * ntp + 1], aq, bh1);
                }
            }

            if (rel + 63 > wid * 16) {
                const int r0 = wid * 16 + lr;
#pragma unroll
                for (int nt = 0; nt < 8; nt++) {
                    const int c0 = rel + nt * 8 + 2 * lc;
                    if (c0 > r0)         sf[nt][0] = -INFINITY;
                    if (c0 + 1 > r0)     sf[nt][1] = -INFINITY;
                    if (c0 > r0 + 8)     sf[nt][2] = -INFINITY;
                    if (c0 + 1 > r0 + 8) sf[nt][3] = -INFINITY;
                }
            }

            float ml0 = -INFINITY, ml1 = -INFINITY;
#pragma unroll
            for (int nt = 0; nt < 8; nt++) {
                ml0 = fmaxf(ml0, fmaxf(sf[nt][0], sf[nt][1]));
                ml1 = fmaxf(ml1, fmaxf(sf[nt][2], sf[nt][3]));
            }
            ml0 = fmaxf(ml0, __shfl_xor_sync(0xffffffffu, ml0, 1));
            ml0 = fmaxf(ml0, __shfl_xor_sync(0xffffffffu, ml0, 2));
            ml1 = fmaxf(ml1, __shfl_xor_sync(0xffffffffu, ml1, 1));
            ml1 = fmaxf(ml1, __shfl_xor_sync(0xffffffffu, ml1, 2));

            const float mn0 = fmaxf(m0, ml0);
            const float mn1 = fmaxf(m1, ml1);
            const float al0 = __expf(m0 - mn0);
            const float al1 = __expf(m1 - mn1);

            float rs0 = 0.f, rs1 = 0.f;
#pragma unroll
            for (int nt = 0; nt < 8; nt++) {
                sf[nt][0] = __expf(sf[nt][0] - mn0);
                sf[nt][1] = __expf(sf[nt][1] - mn0);
                sf[nt][2] = __expf(sf[nt][2] - mn1);
                sf[nt][3] = __expf(sf[nt][3] - mn1);
                rs0 += sf[nt][0] + sf[nt][1];
                rs1 += sf[nt][2] + sf[nt][3];
            }
            rs0 += __shfl_xor_sync(0xffffffffu, rs0, 1);
            rs0 += __shfl_xor_sync(0xffffffffu, rs0, 2);
            rs1 += __shfl_xor_sync(0xffffffffu, rs1, 1);
            rs1 += __shfl_xor_sync(0xffffffffu, rs1, 2);

            l0 = l0 * al0 + rs0;
            l1 = l1 * al1 + rs1;
            m0 = mn0; m1 = mn1;
#pragma unroll
            for (int nt = 0; nt < 8; nt++) {
                O[nt][0] *= al0; O[nt][1] *= al0;
                O[nt][2] *= al1; O[nt][3] *= al1;
            }

            // ---- O += P @ V (single fp16 P) ----
#pragma unroll
            for (int ks = 0; ks < 4; ks++) {
                uint32_t ph[4];
                ph[0] = pack_h2f(sf[2 * ks][0],     sf[2 * ks][1]);
                ph[1] = pack_h2f(sf[2 * ks][2],     sf[2 * ks][3]);
                ph[2] = pack_h2f(sf[2 * ks + 1][0], sf[2 * ks + 1][1]);
                ph[3] = pack_h2f(sf[2 * ks + 1][2], sf[2 * ks + 1][3]);
#pragma unroll
                for (int ntp = 0; ntp < 4; ntp++) {
                    const int n = ntp * 16 + nrow_base;
                    const uint32_t voff = (uint32_t)(n * FS + ks * 8 + (lt & 1) * 4) * 4;
                    uint32_t tv[4];
                    ldm_x4(tv, kbase + 2304 * 4 + voff);
                    uint32_t v0[2] = {tv[0], tv[1]}, v1[2] = {tv[2], tv[3]};
                    mma_fp16(O[2 * ntp],     ph, v0);
                    mma_fp16(O[2 * ntp + 1], ph, v1);
                }
            }
        }
        __syncthreads();
    }

    const float inv0 = 1.0f / l0;
    const float inv1 = 1.0f / l1;
    const int r0 = q0 + wid * 16 + lr;
#pragma unroll
    for (int nt = 0; nt < 8; nt++) {
        const int pcol = h * 32 + nt * 4 + lc;
        float a = O[nt][0] * inv0, bb = O[nt][1] * inv0;
        float ccv = O[nt][2] * inv1, d = O[nt][3] * inv1;
        yhi[(size_t)(b * T_ + r0) * 512 + pcol]     = pack_hi2(a, bb);
        ylo[(size_t)(b * T_ + r0) * 512 + pcol]     = pack_lo2(a, bb);
        yhi[(size_t)(b * T_ + r0 + 8) * 512 + pcol] = pack_hi2(ccv, d);
        ylo[(size_t)(b * T_ + r0 + 8) * 512 + pcol] = pack_lo2(ccv, d);
    }
}

// ---------------------------------------------------------------------------
// Launch (single stream)
// ---------------------------------------------------------------------------
extern "C" void kernel_launch(void* const* d_in, const int* in_sizes, int n_in,
                              void* d_out, int out_size) {
    const float* x      = (const float*)d_in[0];
    const float* sin_t  = (const float*)d_in[1];
    const float* cos_t  = (const float*)d_in[2];
    const float* W_qkv  = (const float*)d_in[3];
    const float* W_proj = (const float*)d_in[4];
    float* out = (float*)d_out;

    float* qkv_ptr = nullptr;
    uint32_t *ahi, *alo, *wthi, *wtlo;
    cudaGetSymbolAddress((void**)&qkv_ptr, g_qkv);
    cudaGetSymbolAddress((void**)&ahi, g_ahi);
    cudaGetSymbolAddress((void**)&alo, g_alo);
    cudaGetSymbolAddress((void**)&wthi, g_wthi);
    cudaGetSymbolAddress((void**)&wtlo, g_wtlo);

    const int M = B_ * T_;
    const int Kp = DIM_ / 2;

    cudaFuncSetAttribute(gemm_pre, cudaFuncAttributeMaxDynamicSharedMemorySize,
                         GEMM_SMEM_BYTES);
    cudaFuncSetAttribute(flash_mma, cudaFuncAttributeMaxDynamicSharedMemorySize,
                         FA_SMEM_BYTES);

    // 1) split x; transpose+split W_qkv; QKV GEMM
    conv_rows<<<(M * Kp) / 256, 256>>>(x, ahi, alo, M * Kp);
    {
        dim3 g(3 * DIM_ / 32, DIM_ / 32);
        conv_tr<<<g, 256>>>(W_qkv, wthi, wtlo, DIM_, 3 * DIM_);
    }
    {
        dim3 g((3 * DIM_) / BN, M / BM);
        gemm_pre<<<g, 256, GEMM_SMEM_BYTES>>>(ahi, alo, wthi, wtlo, qkv_ptr,
                                              M, 3 * DIM_, Kp);
    }

    // 2) merged RoPE(q,k) + V-transpose prepass
    prep_qkv<<<9216, 256>>>(sin_t, cos_t);

    // 3) Flash attention (writes bf16 split output into g_ahi/g_alo)
    {
        dim3 g(T_ / 128, NH_, B_);
        flash_mma<<<g, 256, FA_SMEM_BYTES>>>(ahi, alo);
    }

    // 4) transpose+split W_proj; output projection
    {
        dim3 g(DIM_ / 32, DIM_ / 32);
        conv_tr<<<g, 256>>>(W_proj, wthi, wtlo, DIM_, DIM_);
    }
    {
        dim3 g(DIM_ / BN, M / BM);
        gemm_pre<<<g, 256, GEMM_SMEM_BYTES>>>(ahi, alo, wthi, wtlo, out,
                                              M, DIM_, Kp);
    }
}

// round 17
// speedup vs baseline: 1.4176x; 1.0184x over previous
#include <cuda_runtime.h>
#include <cuda_bf16.h>
#include <cuda_fp16.h>
#include <math.h>
#include <stdint.h>

#define B_   2
#define T_   2048
#define DIM_ 1024
#define NH_  16
#define HD_  64

// fp32 scratch
__device__ float g_qkv[(size_t)B_ * T_ * 3 * DIM_];

// packed scratch
__device__ uint32_t g_ahi[(size_t)4096 * 512];                 // bf16 hi pairs
__device__ uint32_t g_alo[(size_t)4096 * 512];                 // bf16 lo pairs
__device__ uint32_t g_wthi[(size_t)3072 * 512];
__device__ uint32_t g_wtlo[(size_t)3072 * 512];
__device__ uint32_t g_qh [(size_t)B_ * NH_ * T_ * 32];         // fp16 single (scaled q)
__device__ uint32_t g_kh [(size_t)B_ * NH_ * T_ * 32];         // fp16 single (k)
__device__ uint32_t g_vt [(size_t)B_ * NH_ * HD_ * (T_ / 2)];  // fp16x2 transposed v

__device__ __forceinline__ void mma_bf16(float c[4], const uint32_t a[4],
                                         const uint32_t b[2]) {
    asm volatile(
        "mma.sync.aligned.m16n8k16.row.col.f32.bf16.bf16.f32 "
        "{%0,%1,%2,%3}, {%4,%5,%6,%7}, {%8,%9}, {%0,%1,%2,%3};\n"
        : "+f"(c[0]), "+f"(c[1]), "+f"(c[2]), "+f"(c[3])
        : "r"(a[0]), "r"(a[1]), "r"(a[2]), "r"(a[3]), "r"(b[0]), "r"(b[1]));
}

__device__ __forceinline__ void mma_fp16(float c[4], const uint32_t a[4],
                                         const uint32_t b[2]) {
    asm volatile(
        "mma.sync.aligned.m16n8k16.row.col.f32.f16.f16.f32 "
        "{%0,%1,%2,%3}, {%4,%5,%6,%7}, {%8,%9}, {%0,%1,%2,%3};\n"
        : "+f"(c[0]), "+f"(c[1]), "+f"(c[2]), "+f"(c[3])
        : "r"(a[0]), "r"(a[1]), "r"(a[2]), "r"(a[3]), "r"(b[0]), "r"(b[1]));
}

__device__ __forceinline__ void ldm_x4(uint32_t r[4], uint32_t addr) {
    asm volatile("ldmatrix.sync.aligned.m8n8.x4.shared.b16 {%0,%1,%2,%3}, [%4];\n"
                 : "=r"(r[0]), "=r"(r[1]), "=r"(r[2]), "=r"(r[3])
                 : "r"(addr));
}

__device__ __forceinline__ uint32_t pack_hi2(float x, float y) {
    __nv_bfloat162 p = {__float2bfloat16_rn(x), __float2bfloat16_rn(y)};
    return *reinterpret_cast<uint32_t*>(&p);
}
__device__ __forceinline__ uint32_t pack_lo2(float x, float y) {
    float xh = __bfloat162float(__float2bfloat16_rn(x));
    float yh = __bfloat162float(__float2bfloat16_rn(y));
    __nv_bfloat162 p = {__float2bfloat16_rn(x - xh), __float2bfloat16_rn(y - yh)};
    return *reinterpret_cast<uint32_t*>(&p);
}
__device__ __forceinline__ uint32_t pack_h2f(float x, float y) {
    __half2 p = __floats2half2_rn(x, y);
    return *reinterpret_cast<uint32_t*>(&p);
}
__device__ __forceinline__ uint32_t ex2_f16x2(uint32_t a) {
    uint32_t d;
    asm("ex2.approx.f16x2 %0, %1;" : "=r"(d) : "r"(a));
    return d;
}

__device__ __forceinline__ void cp16(uint32_t dst_smem, const void* src) {
    asm volatile("cp.async.cg.shared.global [%0], [%1], 16;\n"
                 :: "r"(dst_smem), "l"(src));
}
#define CP_COMMIT() asm volatile("cp.async.commit_group;\n" ::: "memory")
#define CP_WAIT_1() asm volatile("cp.async.wait_group 1;\n" ::: "memory")
#define CP_WAIT_0() asm volatile("cp.async.wait_group 0;\n" ::: "memory")

// ===========================================================================
// conv_rows: fp32 [M][K] -> hi/lo bf16-pair [M][K/2]
// ===========================================================================
__global__ __launch_bounds__(256) void conv_rows(const float* __restrict__ src,
                                                 uint32_t* __restrict__ hi,
                                                 uint32_t* __restrict__ lo,
                                                 int npairs) {
    const int i = blockIdx.x * blockDim.x + threadIdx.x;
    if (i >= npairs) return;
    float2 f = *reinterpret_cast<const float2*>(src + (size_t)i * 2);
    hi[i] = pack_hi2(f.x, f.y);
    lo[i] = pack_lo2(f.x, f.y);
}

// ===========================================================================
// conv_tr: fp32 W[K][N] -> transposed hi/lo bf16 pairs [N][K/2]
// ===========================================================================
__global__ __launch_bounds__(256) void conv_tr(const float* __restrict__ src,
                                               uint32_t* __restrict__ hi,
                                               uint32_t* __restrict__ lo,
                                               int K, int N) {
    __shared__ float vs[32][33];
    const int tid = threadIdx.x;
    const int n0 = blockIdx.x * 32;
    const int k0 = blockIdx.y * 32;
    const int Kp = K >> 1;
#pragma unroll
    for (int e = 0; e < 4; e++) {
        const int idx = tid + 256 * e;
        const int kl = idx >> 5, nl = idx & 31;
        vs[kl][nl] = src[(size_t)(k0 + kl) * N + n0 + nl];
    }
    __syncthreads();
#pragma unroll
    for (int e = 0; e < 2; e++) {
        const int idx = tid + 256 * e;
        const int nl = idx >> 4, p = idx & 15;
        float f0 = vs[2 * p][nl], f1 = vs[2 * p + 1][nl];
        const size_t o = (size_t)(n0 + nl) * Kp + (k0 >> 1) + p;
        hi[o] = pack_hi2(f0, f1);
        lo[o] = pack_lo2(f0, f1);
    }
}

// ===========================================================================
// gemm_pre (bf16x3, unchanged): BM=128 BN=64, 2-stage cp.async, ldmatrix.
// ===========================================================================
#define BM 128
#define BN 64
#define SA_STRIDE 20
#define SB_STRIDE 20
#define G_STAGE 7680
#define GEMM_SMEM_BYTES (2 * G_STAGE * 4)

__global__ __launch_bounds__(256) void gemm_pre(const uint32_t* __restrict__ Ahi,
                                                const uint32_t* __restrict__ Alo,
                                                const uint32_t* __restrict__ Bthi,
                                                const uint32_t* __restrict__ Btlo,
                                                float* __restrict__ C,
                                                int M, int N, int Kp) {
    extern __shared__ uint32_t sm[];
    const uint32_t sm_u32 = (uint32_t)__cvta_generic_to_shared(sm);

    const int tid  = threadIdx.x;
    const int lane = tid & 31;
    const int wid  = tid >> 5;
    const int wm   = wid & 3;
    const int wn   = wid >> 2;
    const int lr   = lane >> 2;
    const int lc   = lane & 3;
    const int lt   = lane >> 3;
    const int lrw  = lane & 7;

    const int m0 = blockIdx.y * BM;
    const int n0 = blockIdx.x * BN;

    float acc[2][4][4];
#pragma unroll
    for (int mt = 0; mt < 2; mt++)
#pragma unroll
        for (int nt = 0; nt < 4; nt++)
#pragma unroll
            for (int j = 0; j < 4; j++) acc[mt][nt][j] = 0.f;

    const int Kt = Kp / 16;

    auto prefetch = [&](int kt, int s) {
        const int k0p = kt * 16;
        const uint32_t base = sm_u32 + s * G_STAGE * 4;
#pragma unroll
        for (int j = 0; j < 2; j++) {
            const int idx = tid + 256 * j;
            const int row = idx >> 2, ch = idx & 3;
            cp16(base + (row * SA_STRIDE + ch * 4) * 4,
                 &Ahi[(size_t)(m0 + row) * Kp + k0p + ch * 4]);
            cp16(base + (2560 + row * SA_STRIDE + ch * 4) * 4,
                 &Alo[(size_t)(m0 + row) * Kp + k0p + ch * 4]);
        }
        {
            const int row = tid >> 2, ch = tid & 3;
            cp16(base + (5120 + row * SB_STRIDE + ch * 4) * 4,
                 &Bthi[(size_t)(n0 + row) * Kp + k0p + ch * 4]);
            cp16(base + (6400 + row * SB_STRIDE + ch * 4) * 4,
                 &Btlo[(size_t)(n0 + row) * Kp + k0p + ch * 4]);
        }
    };

    prefetch(0, 0);
    CP_COMMIT();

    for (int kt = 0; kt < Kt; kt++) {
        if (kt + 1 < Kt) {
            prefetch(kt + 1, (kt + 1) & 1);
            CP_COMMIT();
            CP_WAIT_1();
        } else {
            CP_WAIT_0();
        }
        __syncthreads();

        const uint32_t sbase = sm_u32 + (kt & 1) * G_STAGE * 4;

#pragma unroll
        for (int ks = 0; ks < 2; ks++) {
            uint32_t ahi[2][4], alo[2][4];
#pragma unroll
            for (int mt = 0; mt < 2; mt++) {
                const int m = wm * 32 + mt * 16 + (lt & 1) * 8 + lrw;
                const uint32_t off = (uint32_t)(m * SA_STRIDE + ks * 8 + (lt >> 1) * 4) * 4;
                ldm_x4(ahi[mt], sbase + off);
                ldm_x4(alo[mt], sbase + 2560 * 4 + off);
            }
#pragma unroll
            for (int ntp = 0; ntp < 2; ntp++) {
                const int n = wn * 32 + ntp * 16 + (lt >> 1) * 8 + lrw;
                const uint32_t off = (uint32_t)(n * SB_STRIDE + ks * 8 + (lt & 1) * 4) * 4;
                uint32_t th[4], tl[4];
                ldm_x4(th, sbase + 5120 * 4 + off);
                ldm_x4(tl, sbase + 6400 * 4 + off);
                uint32_t bh0[2] = {th[0], th[1]}, bh1[2] = {th[2], th[3]};
                uint32_t bl0[2] = {tl[0], tl[1]}, bl1[2] = {tl[2], tl[3]};
#pragma unroll
                for (int mt = 0; mt < 2; mt++) {
                    mma_bf16(acc[mt][2 * ntp],     ahi[mt], bh0);
                    mma_bf16(acc[mt][2 * ntp],     ahi[mt], bl0);
                    mma_bf16(acc[mt][2 * ntp],     alo[mt], bh0);
                    mma_bf16(acc[mt][2 * ntp + 1], ahi[mt], bh1);
                    mma_bf16(acc[mt][2 * ntp + 1], ahi[mt], bl1);
                    mma_bf16(acc[mt][2 * ntp + 1], alo[mt], bh1);
                }
            }
        }
        __syncthreads();
    }

#pragma unroll
    for (int mt = 0; mt < 2; mt++) {
#pragma unroll
        for (int nt = 0; nt < 4; nt++) {
            const int row0 = m0 + wm * 32 + mt * 16 + lr;
            const int col  = n0 + wn * 32 + nt * 8 + lc * 2;
            float2 v0 = make_float2(acc[mt][nt][0], acc[mt][nt][1]);
            float2 v1 = make_float2(acc[mt][nt][2], acc[mt][nt][3]);
            *reinterpret_cast<float2*>(&C[(size_t)row0 * N + col]) = v0;
            *reinterpret_cast<float2*>(&C[(size_t)(row0 + 8) * N + col]) = v1;
        }
    }
}

// ===========================================================================
// prep_qkv: merged RoPE(q,k) + V-transpose (unchanged from R16).
// ===========================================================================
__global__ __launch_bounds__(256) void prep_qkv(const float* __restrict__ sin_t,
                                                const float* __restrict__ cos_t) {
    __shared__ float vs[64][65];
    const int bx = blockIdx.x;
    const int tid = threadIdx.x;

    if (bx < 8192) {
        const int idx = bx * 256 + tid;
        const int i = idx & 31;
        const int h = (idx >> 5) & (NH_ - 1);
        const int bt = idx >> 9;
        const int t = bt & (T_ - 1);
        const int b = bt >> 11;

        const float s = sin_t[t * HD_ + 2 * i];
        const float c = cos_t[t * HD_ + 2 * i];

        const float* row = g_qkv + (size_t)bt * (3 * DIM_);
        const size_t o = ((size_t)(b * NH_ + h) * T_ + t) * 32 + i;

        float2 q = *reinterpret_cast<const float2*>(row + h * HD_ + 2 * i);
        float q0 = (q.x * c - q.y * s) * 0.125f;
        float q1 = (q.y * c + q.x * s) * 0.125f;
        g_qh[o] = pack_h2f(q0, q1);

        float2 k = *reinterpret_cast<const float2*>(row + DIM_ + h * HD_ + 2 * i);
        float k0 = k.x * c - k.y * s;
        float k1 = k.y * c + k.x * s;
        g_kh[o] = pack_h2f(k0, k1);
    } else {
        const int bx2 = bx - 8192;
        const int t0 = (bx2 & 31) * 64;
        const int h  = (bx2 >> 5) & (NH_ - 1);
        const int b  = bx2 >> 9;

        const int r = tid >> 2;
        const int q = (tid & 3) * 16;
        const float* src = g_qkv + (size_t)(b * T_ + t0 + r) * (3 * DIM_)
                           + 2 * DIM_ + h * HD_;
#pragma unroll
        for (int v = 0; v < 4; v++) {
            float4 f4 = *reinterpret_cast<const float4*>(src + q + v * 4);
            vs[r][q + v * 4 + 0] = f4.x;
            vs[r][q + v * 4 + 1] = f4.y;
            vs[r][q + v * 4 + 2] = f4.z;
            vs[r][q + v * 4 + 3] = f4.w;
        }
        __syncthreads();

        const int Tp = T_ / 2;
#pragma unroll
        for (int j = 0; j < 8; j++) {
            const int c = tid + 256 * j;
            const int d = c >> 5, p = c & 31;
            float f0 = vs[2 * p][d], f1 = vs[2 * p + 1][d];
            const size_t o = ((size_t)(b * NH_ + h) * HD_ + d) * Tp + (t0 >> 1) + p;
            g_vt[o] = pack_h2f(f0, f1);
        }
    }
}

// ===========================================================================
// Flash attention: BQ=128, single-fp16 Q/K/V/P, f16x2 ex2 softmax,
// row-sums via ones-MMA.
// smem (uint32): Q [0..4608); stages at 4608 + s*4608: K[0..2304) V[2304..4608)
// ===========================================================================
#define FS 36
#define F_STAGE 4608
#define FA_SMEM_BYTES (3 * 4608 * 4)   // 55,296

__global__ __launch_bounds__(256, 2) void flash_mma(uint32_t* __restrict__ yhi,
                                                    uint32_t* __restrict__ ylo) {
    extern __shared__ uint32_t sm[];
    const uint32_t sm_u32 = (uint32_t)__cvta_generic_to_shared(sm);
    uint32_t* Qh = sm;

    const int tid  = threadIdx.x;
    const int lane = tid & 31;
    const int wid  = tid >> 5;
    const int lr   = lane >> 2;
    const int lc   = lane & 3;
    const int lt   = lane >> 3;
    const int lrw  = lane & 7;

    const int qt = (T_ / 128 - 1) - blockIdx.x;
    const int h  = blockIdx.y;
    const int b  = blockIdx.z;
    const int q0 = qt * 128;
    const size_t hb = (size_t)(b * NH_ + h);
    const int Tp = T_ / 2;
    const float L2E = 1.4426950408889634f;

#pragma unroll
    for (int j = 0; j < 4; j++) {
        const int c = tid + 256 * j;
        const int row = c >> 3, cc = c & 7;
        uint4 vh = *reinterpret_cast<const uint4*>(
            &g_qh[(hb * T_ + q0 + row) * 32 + cc * 4]);
        *reinterpret_cast<uint4*>(&Qh[row * FS + cc * 4]) = vh;
    }

    auto prefetch_kv = [&](int kt, int s) {
        const uint32_t base = sm_u32 + (4608 + s * F_STAGE) * 4;
#pragma unroll
        for (int j = 0; j < 2; j++) {
            const int idx = tid + 256 * j;
            const int row = idx >> 3, ch = idx & 7;
            const uint32_t soff = (row * FS + ch * 4) * 4;
            cp16(base + soff,
                 &g_kh[(hb * T_ + kt * 64 + row) * 32 + ch * 4]);
            cp16(base + 2304 * 4 + soff,
                 &g_vt[(hb * HD_ + row) * Tp + kt * 32 + ch * 4]);
        }
    };

    float O[8][4];
#pragma unroll
    for (int nt = 0; nt < 8; nt++)
#pragma unroll
        for (int j = 0; j < 4; j++) O[nt][j] = 0.f;
    float m0 = -INFINITY, m1 = -INFINITY, l0 = 0.f, l1 = 0.f;

    const int kt_max = 2 * qt + 1;

    prefetch_kv(0, 0);
    CP_COMMIT();

    const int qm = wid * 16 + (lt & 1) * 8 + lrw;
    const int nrow_base = (lt >> 1) * 8 + lrw;

    for (int kt = 0; kt <= kt_max; kt++) {
        if (kt < kt_max) {
            prefetch_kv(kt + 1, (kt + 1) & 1);
            CP_COMMIT();
            CP_WAIT_1();
        } else {
            CP_WAIT_0();
        }
        __syncthreads();

        const uint32_t kbase = sm_u32 + (4608 + (kt & 1) * F_STAGE) * 4;

        const int rel = kt * 64 - q0;
        if (rel <= wid * 16 + 15) {
            // ---- S = Q @ K^T (single fp16) ----
            float sf[8][4];
#pragma unroll
            for (int nt = 0; nt < 8; nt++)
#pragma unroll
                for (int j = 0; j < 4; j++) sf[nt][j] = 0.f;

#pragma unroll
            for (int ks = 0; ks < 4; ks++) {
                const uint32_t qoff = (uint32_t)(qm * FS + ks * 8 + (lt >> 1) * 4) * 4;
                uint32_t aq[4];
                ldm_x4(aq, sm_u32 + qoff);
#pragma unroll
                for (int ntp = 0; ntp < 4; ntp++) {
                    const int n = ntp * 16 + nrow_base;
                    const uint32_t koff = (uint32_t)(n * FS + ks * 8 + (lt & 1) * 4) * 4;
                    uint32_t th[4];
                    ldm_x4(th, kbase + koff);
                    uint32_t bh0[2] = {th[0], th[1]}, bh1[2] = {th[2], th[3]};
                    mma_fp16(sf[2 * ntp],     aq, bh0);
                    mma_fp16(sf[2 * ntp + 1], aq, bh1);
                }
            }

            // ---- causal mask ----
            if (rel + 63 > wid * 16) {
                const int r0 = wid * 16 + lr;
#pragma unroll
                for (int nt = 0; nt < 8; nt++) {
                    const int c0 = rel + nt * 8 + 2 * lc;
                    if (c0 > r0)         sf[nt][0] = -INFINITY;
                    if (c0 + 1 > r0)     sf[nt][1] = -INFINITY;
                    if (c0 > r0 + 8)     sf[nt][2] = -INFINITY;
                    if (c0 + 1 > r0 + 8) sf[nt][3] = -INFINITY;
                }
            }

            // ---- row max ----
            float ml0 = -INFINITY, ml1 = -INFINITY;
#pragma unroll
            for (int nt = 0; nt < 8; nt++) {
                ml0 = fmaxf(ml0, fmaxf(sf[nt][0], sf[nt][1]));
                ml1 = fmaxf(ml1, fmaxf(sf[nt][2], sf[nt][3]));
            }
            ml0 = fmaxf(ml0, __shfl_xor_sync(0xffffffffu, ml0, 1));
            ml0 = fmaxf(ml0, __shfl_xor_sync(0xffffffffu, ml0, 2));
            ml1 = fmaxf(ml1, __shfl_xor_sync(0xffffffffu, ml1, 1));
            ml1 = fmaxf(ml1, __shfl_xor_sync(0xffffffffu, ml1, 2));

            const float mn0 = fmaxf(m0, ml0);
            const float mn1 = fmaxf(m1, ml1);
            const float al0 = __expf(m0 - mn0);
            const float al1 = __expf(m1 - mn1);
            const float mnl0 = mn0 * L2E;
            const float mnl1 = mn1 * L2E;

            // ---- p = ex2.approx.f16x2((s - mn) * log2e), packed fp16 pairs ----
            uint32_t ph_all[4][4];
#pragma unroll
            for (int ks = 0; ks < 4; ks++) {
#pragma unroll
                for (int hh = 0; hh < 2; hh++) {
                    const int nt = 2 * ks + hh;
                    float t0 = fmaf(sf[nt][0], L2E, -mnl0);
                    float t1 = fmaf(sf[nt][1], L2E, -mnl0);
                    float t2 = fmaf(sf[nt][2], L2E, -mnl1);
                    float t3 = fmaf(sf[nt][3], L2E, -mnl1);
                    ph_all[ks][2 * hh]     = ex2_f16x2(pack_h2f(t0, t1));
                    ph_all[ks][2 * hh + 1] = ex2_f16x2(pack_h2f(t2, t3));
                }
            }

            // ---- row sums via ones-MMA ----
            float racc[4] = {0.f, 0.f, 0.f, 0.f};
            const uint32_t ones2[2] = {0x3C003C00u, 0x3C003C00u};
#pragma unroll
            for (int ks = 0; ks < 4; ks++) mma_fp16(racc, ph_all[ks], ones2);

            l0 = l0 * al0 + racc[0];
            l1 = l1 * al1 + racc[2];
            m0 = mn0; m1 = mn1;
#pragma unroll
            for (int nt = 0; nt < 8; nt++) {
                O[nt][0] *= al0; O[nt][1] *= al0;
                O[nt][2] *= al1; O[nt][3] *= al1;
            }

            // ---- O += P @ V ----
#pragma unroll
            for (int ks = 0; ks < 4; ks++) {
#pragma unroll
                for (int ntp = 0; ntp < 4; ntp++) {
                    const int n = ntp * 16 + nrow_base;
                    const uint32_t voff = (uint32_t)(n * FS + ks * 8 + (lt & 1) * 4) * 4;
                    uint32_t tv[4];
                    ldm_x4(tv, kbase + 2304 * 4 + voff);
                    uint32_t v0[2] = {tv[0], tv[1]}, v1[2] = {tv[2], tv[3]};
                    mma_fp16(O[2 * ntp],     ph_all[ks], v0);
                    mma_fp16(O[2 * ntp + 1], ph_all[ks], v1);
                }
            }
        }
        __syncthreads();
    }

    const float inv0 = 1.0f / l0;
    const float inv1 = 1.0f / l1;
    const int r0 = q0 + wid * 16 + lr;
#pragma unroll
    for (int nt = 0; nt < 8; nt++) {
        const int pcol = h * 32 + nt * 4 + lc;
        float a = O[nt][0] * inv0, bb = O[nt][1] * inv0;
        float ccv = O[nt][2] * inv1, d = O[nt][3] * inv1;
        yhi[(size_t)(b * T_ + r0) * 512 + pcol]     = pack_hi2(a, bb);
        ylo[(size_t)(b * T_ + r0) * 512 + pcol]     = pack_lo2(a, bb);
        yhi[(size_t)(b * T_ + r0 + 8) * 512 + pcol] = pack_hi2(ccv, d);
        ylo[(size_t)(b * T_ + r0 + 8) * 512 + pcol] = pack_lo2(ccv, d);
    }
}

// ---------------------------------------------------------------------------
// Launch (single stream)
// ---------------------------------------------------------------------------
extern "C" void kernel_launch(void* const* d_in, const int* in_sizes, int n_in,
                              void* d_out, int out_size) {
    const float* x      = (const float*)d_in[0];
    const float* sin_t  = (const float*)d_in[1];
    const float* cos_t  = (const float*)d_in[2];
    const float* W_qkv  = (const float*)d_in[3];
    const float* W_proj = (const float*)d_in[4];
    float* out = (float*)d_out;

    float* qkv_ptr = nullptr;
    uint32_t *ahi, *alo, *wthi, *wtlo;
    cudaGetSymbolAddress((void**)&qkv_ptr, g_qkv);
    cudaGetSymbolAddress((void**)&ahi, g_ahi);
    cudaGetSymbolAddress((void**)&alo, g_alo);
    cudaGetSymbolAddress((void**)&wthi, g_wthi);
    cudaGetSymbolAddress((void**)&wtlo, g_wtlo);

    const int M = B_ * T_;
    const int Kp = DIM_ / 2;

    cudaFuncSetAttribute(gemm_pre, cudaFuncAttributeMaxDynamicSharedMemorySize,
                         GEMM_SMEM_BYTES);
    cudaFuncSetAttribute(flash_mma, cudaFuncAttributeMaxDynamicSharedMemorySize,
                         FA_SMEM_BYTES);

    // 1) split x; transpose+split W_qkv; QKV GEMM
    conv_rows<<<(M * Kp) / 256, 256>>>(x, ahi, alo, M * Kp);
    {
        dim3 g(3 * DIM_ / 32, DIM_ / 32);
        conv_tr<<<g, 256>>>(W_qkv, wthi, wtlo, DIM_, 3 * DIM_);
    }
    {
        dim3 g((3 * DIM_) / BN, M / BM);
        gemm_pre<<<g, 256, GEMM_SMEM_BYTES>>>(ahi, alo, wthi, wtlo, qkv_ptr,
                                              M, 3 * DIM_, Kp);
    }

    // 2) merged RoPE(q,k) + V-transpose prepass
    prep_qkv<<<9216, 256>>>(sin_t, cos_t);

    // 3) Flash attention (writes bf16 split output into g_ahi/g_alo)
    {
        dim3 g(T_ / 128, NH_, B_);
        flash_mma<<<g, 256, FA_SMEM_BYTES>>>(ahi, alo);
    }

    // 4) transpose+split W_proj; output projection
    {
        dim3 g(DIM_ / 32, DIM_ / 32);
        conv_tr<<<g, 256>>>(W_proj, wthi, wtlo, DIM_, DIM_);
    }
    {
        dim3 g(DIM_ / BN, M / BM);
        gemm_pre<<<g, 256, GEMM_SMEM_BYTES>>>(ahi, alo, wthi, wtlo, out,
                                              M, DIM_, Kp);
    }
}